// round 13
// baseline (speedup 1.0000x reference)
#include <cuda_runtime.h>
#include <cuda_bf16.h>
#include <cstdint>
#include <cstddef>

#define NN 50000
#define NE 600000
#define DD 128
#define HH 256
#define TM 128

// ============================ device scratch ================================
__device__ float g_agg[(size_t)NN * DD];
__device__ float g_PQ[(size_t)NN * 512];   // per-node [P|Q] for msg MLP
__device__ float g_R[(size_t)NN * HH];     // per-node R = feat@uW0b + updb0
// weights transposed to [N][K] row-major, bf16 hi/lo split
__device__ __nv_bfloat16 g_c0h[512 * DD], g_c0l[512 * DD];   // msg [W0a|W0b]^T : [512][128]
__device__ __nv_bfloat16 g_uah[HH * DD],  g_ual[HH * DD];    // upd W0a^T: [256][128]
__device__ __nv_bfloat16 g_ubh[HH * DD],  g_ubl[HH * DD];    // upd W0b^T: [256][128]
__device__ __nv_bfloat16 g_mW1h[DD * HH], g_mW1l[DD * HH];   // msg W1^T: [128][256]
__device__ __nv_bfloat16 g_uW1h[DD * HH], g_uW1l[DD * HH];   // upd W1^T: [128][256]

// ============================ PTX helpers ===================================
__device__ __forceinline__ uint32_t smem_u32(const void* p) {
    uint32_t a;
    asm("{ .reg .u64 t; cvta.to.shared.u64 t, %1; cvt.u32.u64 %0, t; }" : "=r"(a) : "l"(p));
    return a;
}
__device__ __forceinline__ void ldsm_x4(uint32_t& r0, uint32_t& r1, uint32_t& r2,
                                        uint32_t& r3, uint32_t addr) {
    asm volatile("ldmatrix.sync.aligned.m8n8.x4.shared.b16 {%0,%1,%2,%3}, [%4];"
                 : "=r"(r0), "=r"(r1), "=r"(r2), "=r"(r3) : "r"(addr));
}
__device__ __forceinline__ void mma_bf16(float* d, const uint32_t* a,
                                         uint32_t b0, uint32_t b1) {
    asm volatile(
        "mma.sync.aligned.m16n8k16.row.col.f32.bf16.bf16.f32 "
        "{%0,%1,%2,%3},{%4,%5,%6,%7},{%8,%9},{%0,%1,%2,%3};"
        : "+f"(d[0]), "+f"(d[1]), "+f"(d[2]), "+f"(d[3])
        : "r"(a[0]), "r"(a[1]), "r"(a[2]), "r"(a[3]), "r"(b0), "r"(b1));
}
__device__ __forceinline__ uint32_t pack_bf16(float a, float b) {
    __nv_bfloat162 t = __floats2bfloat162_rn(a, b);
    return *reinterpret_cast<uint32_t*>(&t);
}
__device__ __forceinline__ void cpa16(uint32_t dst, const void* src) {
    asm volatile("cp.async.cg.shared.global [%0], [%1], 16;"
                 :: "r"(dst), "l"(src) : "memory");
}
#define CP_COMMIT() asm volatile("cp.async.commit_group;" ::: "memory")
#define CP_WAIT(n)  asm volatile("cp.async.wait_group %0;" :: "n"(n) : "memory")
__device__ __forceinline__ void red_add2(float* a, float v0, float v1) {
    asm volatile("red.global.add.v2.f32 [%0], {%1, %2};"
                 :: "l"(a), "f"(v0), "f"(v1) : "memory");
}
__device__ __forceinline__ void bar_g(int id) {
    asm volatile("bar.sync %0, 64;" :: "r"(id) : "memory");
}
__device__ __forceinline__ uint32_t swz64(uint32_t off) {   // conflict-free 64B rows
    return off ^ ((off >> 3) & 0x30);
}

// store float4 -> hi/lo bf16x2 pairs at byte offset off in two tiles
__device__ __forceinline__ void split_store(char* smc, int hi_base, int lo_base,
                                            int off, float4 v) {
    __nv_bfloat16 h0 = __float2bfloat16(v.x), h1 = __float2bfloat16(v.y);
    __nv_bfloat16 h2 = __float2bfloat16(v.z), h3 = __float2bfloat16(v.w);
    uint2 H, L;
    H.x = pack_bf16(v.x, v.y);
    H.y = pack_bf16(v.z, v.w);
    L.x = pack_bf16(v.x - __bfloat162float(h0), v.y - __bfloat162float(h1));
    L.y = pack_bf16(v.z - __bfloat162float(h2), v.w - __bfloat162float(h3));
    *reinterpret_cast<uint2*>(smc + hi_base + off) = H;
    *reinterpret_cast<uint2*>(smc + lo_base + off) = L;
}

__device__ __forceinline__ float4 relu_add4(float4 p, float4 q) {
    float4 v;
    v.x = fmaxf(p.x + q.x, 0.f);
    v.y = fmaxf(p.y + q.y, 0.f);
    v.z = fmaxf(p.z + q.z, 0.f);
    v.w = fmaxf(p.w + q.w, 0.f);
    return v;
}

// =========================== prelude kernels ================================
__global__ void zero_agg_kernel() {
    const size_t n4 = (size_t)NN * DD / 4;
    float4 z = make_float4(0.f, 0.f, 0.f, 0.f);
    for (size_t i = (size_t)blockIdx.x * blockDim.x + threadIdx.x; i < n4;
         i += (size_t)gridDim.x * blockDim.x)
        reinterpret_cast<float4*>(g_agg)[i] = z;
}

__device__ __forceinline__ void put_split(__nv_bfloat16* h, __nv_bfloat16* l,
                                          int idx, float w) {
    __nv_bfloat16 hi = __float2bfloat16(w);
    h[idx] = hi;
    l[idx] = __float2bfloat16(w - __bfloat162float(hi));
}

__global__ void conv_w_kernel(const float* __restrict__ mW0, const float* __restrict__ uW0,
                              const float* __restrict__ mW1, const float* __restrict__ uW1) {
    int i = blockIdx.x * blockDim.x + threadIdx.x;
    if (i >= 196608) return;
    if (i < 65536) {                      // msg [W0a|W0b]^T
        int n = i >> 7, k = i & 127;
        float w = (n < 256) ? mW0[k * HH + n] : mW0[(128 + k) * HH + (n - 256)];
        put_split(g_c0h, g_c0l, n * DD + k, w);
    } else if (i < 98304) {               // upd W0a^T (agg part)
        int j = i - 65536, n = j >> 7, k = j & 127;
        put_split(g_uah, g_ual, n * DD + k, uW0[k * HH + n]);
    } else if (i < 131072) {              // upd W0b^T (feat part)
        int j = i - 98304, n = j >> 7, k = j & 127;
        put_split(g_ubh, g_ubl, n * DD + k, uW0[(DD + k) * HH + n]);
    } else if (i < 163840) {              // msg W1^T
        int j = i - 131072, k = j >> 7, n = j & 127;
        put_split(g_mW1h, g_mW1l, n * HH + k, mW1[j]);
    } else {                              // upd W1^T
        int j = i - 163840, k = j >> 7, n = j & 127;
        put_split(g_uW1h, g_uW1l, n * HH + k, uW1[j]);
    }
}

// generic B-chunk stager: nrows x 32 K-cols, BROW=80, 512 threads
__device__ __forceinline__ void stage_b(uint32_t bbase, int tid,
                                        const __nv_bfloat16* Wh,
                                        const __nv_bfloat16* Wl,
                                        int row_base, int chunk, int nrows,
                                        int kstride, int bhalf) {
    #pragma unroll
    for (int i = 0; i < 2; ++i) {
        int idx = tid + i * 512;
        if (idx < nrows * 4) {
            int row = idx >> 2, seg = idx & 3;
            uint32_t d = bbase + (uint32_t)(row * 80 + seg * 16);
            const int so = (row_base + row) * kstride + chunk * 32 + seg * 8;
            cpa16(d, Wh + so);
            cpa16(d + bhalf, Wl + so);
        }
    }
}

// ======================= PQ+R precompute kernel =============================
#define P_B0    0
#define P_UB0   1024
#define P_AHI   4096
#define P_ALO   (4096 + 34816)          // 38912
#define P_B     (38912 + 34816)         // 73728
#define P_BHALF 20480
#define P_BBUF  40960
#define P_SMEM  (73728 + 2 * P_BBUF)    // 155648
#define AROW2   272

__global__ void __launch_bounds__(512, 1) pq_kernel(const float* __restrict__ feat,
                                                    const float* __restrict__ b0,
                                                    const float* __restrict__ ub0) {
    extern __shared__ char smc[];
    const uint32_t sb = smem_u32(smc);
    const int tid  = threadIdx.x;
    const int wid  = tid >> 5;
    const int lane = tid & 31;
    const int wr   = wid & 3;
    const int wc   = wid >> 2;
    const int lrow = ((lane >> 3) & 1) * 8 + (lane & 7);
    const int lcol = (lane >> 4) * 8;
    float* b0s  = reinterpret_cast<float*>(smc + P_B0);
    float* ub0s = reinterpret_cast<float*>(smc + P_UB0);

    const int tile0 = blockIdx.x * TM;
    if (tid < 256) b0s[tid] = b0[tid];
    else ub0s[tid - 256] = ub0[tid - 256];

    stage_b(sb + P_B, tid, g_c0h, g_c0l, 0, 0, 256, DD, P_BHALF);
    CP_COMMIT();

    {
        const float4* f4 = reinterpret_cast<const float4*>(feat);
        #pragma unroll
        for (int it = 0; it < 8; ++it) {
            int ci = tid + it * 512;
            int r  = ci >> 5;
            int c4 = ci & 31;
            int node = tile0 + r;
            float4 v = make_float4(0.f, 0.f, 0.f, 0.f);
            if (node < NN) v = f4[(size_t)node * 32 + c4];
            split_store(smc, P_AHI, P_ALO, r * AROW2 + c4 * 8, v);
        }
    }
    __syncthreads();

    for (int h = 0; h < 3; ++h) {
        float acc[2][8][4];
        #pragma unroll
        for (int m = 0; m < 2; ++m)
            #pragma unroll
            for (int n = 0; n < 8; ++n)
                #pragma unroll
                for (int q = 0; q < 4; ++q) acc[m][n][q] = 0.f;

        for (int c = 0; c < 4; ++c) {
            int gg = h * 4 + c;
            if (gg < 11) {
                int gn = gg + 1, hn = gn >> 2, cn = gn & 3;
                const __nv_bfloat16* Wh = (hn < 2) ? g_c0h : g_ubh;
                const __nv_bfloat16* Wl = (hn < 2) ? g_c0l : g_ubl;
                int rb = (hn == 1) ? 256 : 0;
                stage_b(sb + P_B + (uint32_t)(gn & 1) * P_BBUF, tid,
                        Wh, Wl, rb, cn, 256, DD, P_BHALF);
            }
            CP_COMMIT();
            CP_WAIT(1);
            __syncthreads();
            const uint32_t bbase = sb + P_B + (uint32_t)(gg & 1) * P_BBUF;
            #pragma unroll
            for (int ks = 0; ks < 2; ++ks) {
                const int kA = c * 32 + ks * 16;
                uint32_t ah[2][4], al[2][4];
                #pragma unroll
                for (int mt = 0; mt < 2; ++mt) {
                    uint32_t aaddr = sb + P_AHI +
                        (uint32_t)((wr * 32 + mt * 16 + lrow) * AROW2 + (kA + lcol) * 2);
                    ldsm_x4(ah[mt][0], ah[mt][1], ah[mt][2], ah[mt][3], aaddr);
                    ldsm_x4(al[mt][0], al[mt][1], al[mt][2], al[mt][3],
                            aaddr + (P_ALO - P_AHI));
                }
                #pragma unroll
                for (int np = 0; np < 4; ++np) {
                    uint32_t baddr = bbase +
                        (uint32_t)((wc * 64 + np * 16 + lrow) * 80 + (ks * 16 + lcol) * 2);
                    uint32_t bh0, bh1, bh2, bh3, bl0, bl1, bl2, bl3;
                    ldsm_x4(bh0, bh1, bh2, bh3, baddr);
                    ldsm_x4(bl0, bl1, bl2, bl3, baddr + P_BHALF);
                    const int nb = np * 2;
                    #pragma unroll
                    for (int mt = 0; mt < 2; ++mt) {
                        mma_bf16(acc[mt][nb],     ah[mt], bh0, bh2);
                        mma_bf16(acc[mt][nb + 1], ah[mt], bh1, bh3);
                        mma_bf16(acc[mt][nb],     al[mt], bh0, bh2);
                        mma_bf16(acc[mt][nb + 1], al[mt], bh1, bh3);
                        mma_bf16(acc[mt][nb],     ah[mt], bl0, bl2);
                        mma_bf16(acc[mt][nb + 1], ah[mt], bl1, bl3);
                    }
                }
            }
            __syncthreads();
        }

        #pragma unroll
        for (int mt = 0; mt < 2; ++mt)
            #pragma unroll
            for (int nt = 0; nt < 8; ++nt) {
                int cc = wc * 64 + nt * 8 + 2 * (lane & 3);
                int r0 = wr * 32 + mt * 16 + (lane >> 2);
                int r1 = r0 + 8;
                float* d = acc[mt][nt];
                float bb0 = (h == 0) ? b0s[cc]      : (h == 2) ? ub0s[cc]     : 0.f;
                float bb1 = (h == 0) ? b0s[cc + 1]  : (h == 2) ? ub0s[cc + 1] : 0.f;
                int n0 = tile0 + r0, n1 = tile0 + r1;
                if (h < 2) {
                    int co = h * 256 + cc;
                    if (n0 < NN)
                        *reinterpret_cast<float2*>(g_PQ + (size_t)n0 * 512 + co) =
                            make_float2(d[0] + bb0, d[1] + bb1);
                    if (n1 < NN)
                        *reinterpret_cast<float2*>(g_PQ + (size_t)n1 * 512 + co) =
                            make_float2(d[2] + bb0, d[3] + bb1);
                } else {
                    if (n0 < NN)
                        *reinterpret_cast<float2*>(g_R + (size_t)n0 * HH + cc) =
                            make_float2(d[0] + bb0, d[1] + bb1);
                    if (n1 < NN)
                        *reinterpret_cast<float2*>(g_R + (size_t)n1 * HH + cc) =
                            make_float2(d[2] + bb0, d[3] + bb1);
                }
            }
    }
}

// ========= edge kernel (persistent, EIGHT 2-warp groups, warp tile 32x64) ====
// Group g (warps 2g,2g+1; 64 thr) streams its own 32-row edge tiles.
// Warp tile 32x64 -> A fragments shared by only 2 warps (-25% LDSM traffic).
// W1 smem-resident in COMPACT SW64 layout (64B rows, conflict-free).
#define TME    32
#define E_B1   0                       // 128 floats
#define E_TO   512                     // 8 g x 2 parity x 32 ints
#define E_A    4096                    // 8 groups x 10240 (2 bufs x (hi2560+lo2560))
#define E_BH   (4096 + 81920)          // 86016: 8 chunks x 8192 (compact hi)
#define E_BL   (86016 + 65536)         // 151552: compact lo
#define E_SMEM (151552 + 65536)        // 217088

#define EDGE_T32 (NE / TME)            // 18750

__global__ void __launch_bounds__(512, 1) edge_kernel(
    const int* __restrict__ from_idx, const int* __restrict__ to_idx,
    const float* __restrict__ b1)
{
    extern __shared__ char smc[];
    const uint32_t sb = smem_u32(smc);
    const int tid  = threadIdx.x;
    const int wid  = tid >> 5;
    const int lane = tid & 31;
    const int g    = wid >> 1;            // group 0..7
    const int gwid = wid & 1;             // N-half (64 cols)
    const int lrow = ((lane >> 3) & 1) * 8 + (lane & 7);
    const int lcol = (lane >> 4) * 8;
    const int barid = 1 + g;

    float* b1s = reinterpret_cast<float*>(smc + E_B1);
    if (tid < 128) b1s[tid] = b1[tid];

    // ---- stage resident W1 hi/lo once, compact SW64 layout ----
    #pragma unroll
    for (int i = 0; i < 8; ++i) {
        int idx = tid + i * 512;          // cb*512 + row*4 + seg
        int cb = idx >> 9, rs = idx & 511;
        int row = rs >> 2, seg = rs & 3;
        uint32_t d = sb + E_BH + (uint32_t)(cb * 8192) + swz64(row * 64 + seg * 16);
        int so = row * HH + cb * 32 + seg * 8;
        cpa16(d, g_mW1h + so);
        cpa16(d + (E_BL - E_BH), g_mW1l + so);
    }
    CP_COMMIT();
    CP_WAIT(0);
    __syncthreads();                      // last full-CTA sync

    const float4* pq4 = reinterpret_cast<const float4*>(g_PQ);
    const int ptid = tid & 63;            // group-local thread id
    const int r  = ptid >> 1;             // local row 0..31
    const int sg = ptid & 1;              // half-row producer (4 f4 of P + 4 of Q)
    const int ga = E_A + g * 10240;       // group A buffers

    int tcnt = 0;
    for (int tile = blockIdx.x * 8 + g; tile < EDGE_T32; tile += gridDim.x * 8, ++tcnt) {
        const int tile0 = tile * TME;

        int fr = from_idx[tile0 + r];
        int to = to_idx[tile0 + r];
        int* stob = reinterpret_cast<int*>(smc + E_TO + (g * 2 + (tcnt & 1)) * 128);
        if (sg == 0) stob[r] = to;

        const size_t prow = (size_t)fr * 128 + sg * 4;        // float4 units
        const size_t qrow = (size_t)to * 128 + 64 + sg * 4;
        const int off0 = r * 80 + sg * 32;                    // byte off of f4 j=0

        // produce chunk 0 into buf 0 (4 f4 P + 4 f4 Q per thread)
        {
            #pragma unroll
            for (int j = 0; j < 4; ++j) {
                float4 p = pq4[prow + j];
                float4 q = pq4[qrow + j];
                split_store(smc, ga, ga + 2560, off0 + j * 8, relu_add4(p, q));
            }
        }
        bar_g(barid);

        float ac2[2][8][4];
        #pragma unroll
        for (int m = 0; m < 2; ++m)
            #pragma unroll
            for (int n = 0; n < 8; ++n)
                #pragma unroll
                for (int q = 0; q < 4; ++q) ac2[m][n][q] = 0.f;

        #pragma unroll
        for (int c = 0; c < 8; ++c) {
            // prefetch first half of next chunk's gathers
            float4 p0, p1, q0, q1;
            if (c < 7) {
                p0 = pq4[prow + (c + 1) * 8];
                p1 = pq4[prow + (c + 1) * 8 + 1];
                q0 = pq4[qrow + (c + 1) * 8];
                q1 = pq4[qrow + (c + 1) * 8 + 1];
            }
            const uint32_t abase = sb + (uint32_t)(ga + (c & 1) * 5120);
            const uint32_t bbase = sb + E_BH + (uint32_t)(c * 8192);
            #pragma unroll
            for (int ks = 0; ks < 2; ++ks) {
                uint32_t ah[2][4], al[2][4];
                #pragma unroll
                for (int mt = 0; mt < 2; ++mt) {
                    uint32_t aaddr = abase +
                        (uint32_t)((mt * 16 + lrow) * 80 + (ks * 16 + lcol) * 2);
                    ldsm_x4(ah[mt][0], ah[mt][1], ah[mt][2], ah[mt][3], aaddr);
                    ldsm_x4(al[mt][0], al[mt][1], al[mt][2], al[mt][3], aaddr + 2560);
                }
                #pragma unroll
                for (int np = 0; np < 4; ++np) {
                    uint32_t baddr = bbase +
                        swz64((uint32_t)((gwid * 64 + np * 16 + lrow) * 64 +
                                         ks * 32 + lcol * 2));
                    uint32_t bh0, bh1, bh2, bh3, bl0, bl1, bl2, bl3;
                    ldsm_x4(bh0, bh1, bh2, bh3, baddr);
                    ldsm_x4(bl0, bl1, bl2, bl3, baddr + (E_BL - E_BH));
                    const int nb = np * 2;
                    #pragma unroll
                    for (int mt = 0; mt < 2; ++mt) {
                        mma_bf16(ac2[mt][nb],     ah[mt], bh0, bh2);
                        mma_bf16(ac2[mt][nb + 1], ah[mt], bh1, bh3);
                        mma_bf16(ac2[mt][nb],     al[mt], bh0, bh2);
                        mma_bf16(ac2[mt][nb + 1], al[mt], bh1, bh3);
                        mma_bf16(ac2[mt][nb],     ah[mt], bl0, bl2);
                        mma_bf16(ac2[mt][nb + 1], ah[mt], bl1, bl3);
                    }
                }
            }
            if (c < 7) {
                const int ab = ga + ((c + 1) & 1) * 5120;
                split_store(smc, ab, ab + 2560, off0,     relu_add4(p0, q0));
                split_store(smc, ab, ab + 2560, off0 + 8, relu_add4(p1, q1));
                // second half loaded inline (latency amortized across groups)
                float4 p2 = pq4[prow + (c + 1) * 8 + 2];
                float4 p3 = pq4[prow + (c + 1) * 8 + 3];
                float4 q2 = pq4[qrow + (c + 1) * 8 + 2];
                float4 q3 = pq4[qrow + (c + 1) * 8 + 3];
                split_store(smc, ab, ab + 2560, off0 + 16, relu_add4(p2, q2));
                split_store(smc, ab, ab + 2560, off0 + 24, relu_add4(p3, q3));
            }
            bar_g(barid);
        }

        // ---- epilogue: bias+relu, vectorized red scatter ----
        const int* stor =
            reinterpret_cast<const int*>(smc + E_TO + (g * 2 + (tcnt & 1)) * 128);
        #pragma unroll
        for (int mt = 0; mt < 2; ++mt)
            #pragma unroll
            for (int nt = 0; nt < 8; ++nt) {
                int cc = gwid * 64 + nt * 8 + 2 * (lane & 3);
                int r0 = mt * 16 + (lane >> 2);
                int r1 = r0 + 8;
                float* d = ac2[mt][nt];
                float v0 = fmaxf(d[0] + b1s[cc], 0.f), v1 = fmaxf(d[1] + b1s[cc + 1], 0.f);
                float v2 = fmaxf(d[2] + b1s[cc], 0.f), v3 = fmaxf(d[3] + b1s[cc + 1], 0.f);
                red_add2(g_agg + (size_t)stor[r0] * DD + cc, v0, v1);
                red_add2(g_agg + (size_t)stor[r1] * DD + cc, v2, v3);
            }
    }
}

// ============================ node kernel (K-folded) ========================
#define SM_B1   1024
#define SM_AHI  4096
#define SM_ALO  (4096 + 67584)          // 71680
#define SM_B    (71680 + 67584)         // 139264
#define N_BHALF 20480
#define N_BBUF  40960
#define N_SMEM  (139264 + 2 * N_BBUF)   // 221184
#define AROW 528

__global__ void __launch_bounds__(512, 1) node_kernel(
    const float* __restrict__ feat,
    const float* __restrict__ b1,
    float* __restrict__ outp)
{
    extern __shared__ char smc[];
    const uint32_t sb = smem_u32(smc);
    const int tid  = threadIdx.x;
    const int wid  = tid >> 5;
    const int lane = tid & 31;
    const int wr   = wid & 3;
    const int wc   = wid >> 2;
    const int lrow = ((lane >> 3) & 1) * 8 + (lane & 7);
    const int lcol = (lane >> 4) * 8;

    float* b1s = reinterpret_cast<float*>(smc + SM_B1);

    const int tile0 = blockIdx.x * TM;

    if (tid < 128) b1s[tid] = b1[tid];

    stage_b(sb + SM_B, tid, g_uah, g_ual, 0, 0, 256, DD, N_BHALF);
    CP_COMMIT();
    __syncthreads();

    // gather agg tile [128 x 128]
    {
        const float4* a4 = reinterpret_cast<const float4*>(g_agg);
        #pragma unroll
        for (int it = 0; it < 8; ++it) {
            int ci = tid + it * 512;
            int r  = ci >> 5;
            int c4 = ci & 31;
            int node = tile0 + r;
            float4 v = make_float4(0.f, 0.f, 0.f, 0.f);
            if (node < NN) v = a4[(size_t)node * 32 + c4];
            split_store(smc, SM_AHI, SM_ALO, r * AROW + c4 * 8, v);
        }
    }
    __syncthreads();

    // GEMM1: S = agg@uW0a, K=128 -> 4 chunks
    float acc[2][8][4];
    #pragma unroll
    for (int m = 0; m < 2; ++m)
        #pragma unroll
        for (int n = 0; n < 8; ++n)
            #pragma unroll
            for (int q = 0; q < 4; ++q) acc[m][n][q] = 0.f;

    for (int c = 0; c < 4; ++c) {
        if (c < 3)
            stage_b(sb + SM_B + (uint32_t)((c + 1) & 1) * N_BBUF, tid,
                    g_uah, g_ual, 0, c + 1, 256, DD, N_BHALF);
        CP_COMMIT();
        CP_WAIT(1);
        __syncthreads();
        const uint32_t bbase = sb + SM_B + (uint32_t)(c & 1) * N_BBUF;
        #pragma unroll
        for (int ks = 0; ks < 2; ++ks) {
            const int kA = c * 32 + ks * 16;
            uint32_t ah[2][4], al[2][4];
            #pragma unroll
            for (int mt = 0; mt < 2; ++mt) {
                uint32_t aaddr = sb + SM_AHI +
                    (uint32_t)((wr * 32 + mt * 16 + lrow) * AROW + (kA + lcol) * 2);
                ldsm_x4(ah[mt][0], ah[mt][1], ah[mt][2], ah[mt][3], aaddr);
                ldsm_x4(al[mt][0], al[mt][1], al[mt][2], al[mt][3],
                        aaddr + (SM_ALO - SM_AHI));
            }
            #pragma unroll
            for (int np = 0; np < 4; ++np) {
                uint32_t baddr = bbase +
                    (uint32_t)((wc * 64 + np * 16 + lrow) * 80 + (ks * 16 + lcol) * 2);
                uint32_t bh0, bh1, bh2, bh3, bl0, bl1, bl2, bl3;
                ldsm_x4(bh0, bh1, bh2, bh3, baddr);
                ldsm_x4(bl0, bl1, bl2, bl3, baddr + N_BHALF);
                const int nb = np * 2;
                #pragma unroll
                for (int mt = 0; mt < 2; ++mt) {
                    mma_bf16(acc[mt][nb],     ah[mt], bh0, bh2);
                    mma_bf16(acc[mt][nb + 1], ah[mt], bh1, bh3);
                    mma_bf16(acc[mt][nb],     al[mt], bh0, bh2);
                    mma_bf16(acc[mt][nb + 1], al[mt], bh1, bh3);
                    mma_bf16(acc[mt][nb],     ah[mt], bl0, bl2);
                    mma_bf16(acc[mt][nb + 1], ah[mt], bl1, bl3);
                }
            }
        }
        __syncthreads();
    }

    stage_b(sb + SM_B, tid, g_uW1h, g_uW1l, 0, 0, 128, HH, N_BHALF);
    CP_COMMIT();

    // epilogue1: h = relu(S + R[n]) back into A tiles
    #pragma unroll
    for (int mt = 0; mt < 2; ++mt)
        #pragma unroll
        for (int nt = 0; nt < 8; ++nt) {
            int cc = wc * 64 + nt * 8 + 2 * (lane & 3);
            int r0 = wr * 32 + mt * 16 + (lane >> 2);
            int n0 = tile0 + r0, n1 = n0 + 8;
            float* d = acc[mt][nt];
            float2 R0 = make_float2(0.f, 0.f), R1 = make_float2(0.f, 0.f);
            if (n0 < NN) R0 = *reinterpret_cast<const float2*>(g_R + (size_t)n0 * HH + cc);
            if (n1 < NN) R1 = *reinterpret_cast<const float2*>(g_R + (size_t)n1 * HH + cc);
            float v0 = fmaxf(d[0] + R0.x, 0.f), v1 = fmaxf(d[1] + R0.y, 0.f);
            float v2 = fmaxf(d[2] + R1.x, 0.f), v3 = fmaxf(d[3] + R1.y, 0.f);
            __nv_bfloat16 h0 = __float2bfloat16(v0), h1 = __float2bfloat16(v1);
            __nv_bfloat16 h2 = __float2bfloat16(v2), h3 = __float2bfloat16(v3);
            int o0 = r0 * AROW + cc * 2;
            int o1 = (r0 + 8) * AROW + cc * 2;
            *reinterpret_cast<uint32_t*>(smc + SM_AHI + o0) = pack_bf16(v0, v1);
            *reinterpret_cast<uint32_t*>(smc + SM_AHI + o1) = pack_bf16(v2, v3);
            *reinterpret_cast<uint32_t*>(smc + SM_ALO + o0) =
                pack_bf16(v0 - __bfloat162float(h0), v1 - __bfloat162float(h1));
            *reinterpret_cast<uint32_t*>(smc + SM_ALO + o1) =
                pack_bf16(v2 - __bfloat162float(h2), v3 - __bfloat162float(h3));
        }

    // GEMM2: M = h@uW1, K=256 -> 8 chunks
    float ac2[2][4][4];
    #pragma unroll
    for (int m = 0; m < 2; ++m)
        #pragma unroll
        for (int n = 0; n < 4; ++n)
            #pragma unroll
            for (int q = 0; q < 4; ++q) ac2[m][n][q] = 0.f;

    for (int c = 0; c < 8; ++c) {
        if (c < 7)
            stage_b(sb + SM_B + (uint32_t)((c + 1) & 1) * N_BBUF, tid,
                    g_uW1h, g_uW1l, 0, c + 1, 128, HH, N_BHALF);
        CP_COMMIT();
        CP_WAIT(1);
        __syncthreads();
        const uint32_t bbase = sb + SM_B + (uint32_t)(c & 1) * N_BBUF;
        #pragma unroll
        for (int ks = 0; ks < 2; ++ks) {
            const int kA = c * 32 + ks * 16;
            uint32_t ah[2][4], al[2][4];
            #pragma unroll
            for (int mt = 0; mt < 2; ++mt) {
                uint32_t aaddr = sb + SM_AHI +
                    (uint32_t)((wr * 32 + mt * 16 + lrow) * AROW + (kA + lcol) * 2);
                ldsm_x4(ah[mt][0], ah[mt][1], ah[mt][2], ah[mt][3], aaddr);
                ldsm_x4(al[mt][0], al[mt][1], al[mt][2], al[mt][3],
                        aaddr + (SM_ALO - SM_AHI));
            }
            #pragma unroll
            for (int np = 0; np < 2; ++np) {
                uint32_t baddr = bbase +
                    (uint32_t)((wc * 32 + np * 16 + lrow) * 80 + (ks * 16 + lcol) * 2);
                uint32_t bh0, bh1, bh2, bh3, bl0, bl1, bl2, bl3;
                ldsm_x4(bh0, bh1, bh2, bh3, baddr);
                ldsm_x4(bl0, bl1, bl2, bl3, baddr + N_BHALF);
                const int nb = np * 2;
                #pragma unroll
                for (int mt = 0; mt < 2; ++mt) {
                    mma_bf16(ac2[mt][nb],     ah[mt], bh0, bh2);
                    mma_bf16(ac2[mt][nb + 1], ah[mt], bh1, bh3);
                    mma_bf16(ac2[mt][nb],     al[mt], bh0, bh2);
                    mma_bf16(ac2[mt][nb + 1], al[mt], bh1, bh3);
                    mma_bf16(ac2[mt][nb],     ah[mt], bl0, bl2);
                    mma_bf16(ac2[mt][nb + 1], ah[mt], bl1, bl3);
                }
            }
        }
        __syncthreads();
    }

    // epilogue2: residual store
    #pragma unroll
    for (int mt = 0; mt < 2; ++mt)
        #pragma unroll
        for (int nt = 0; nt < 4; ++nt) {
            int cc = wc * 32 + nt * 8 + 2 * (lane & 3);
            int r0 = wr * 32 + mt * 16 + (lane >> 2);
            int r1 = r0 + 8;
            float* d = ac2[mt][nt];
            float v0 = fmaxf(d[0] + b1s[cc], 0.f), v1 = fmaxf(d[1] + b1s[cc + 1], 0.f);
            float v2 = fmaxf(d[2] + b1s[cc], 0.f), v3 = fmaxf(d[3] + b1s[cc + 1], 0.f);
            int n0 = tile0 + r0, n1 = tile0 + r1;
            if (n0 < NN) {
                float2 f = *reinterpret_cast<const float2*>(feat + (size_t)n0 * DD + cc);
                *reinterpret_cast<float2*>(outp + (size_t)n0 * DD + cc) =
                    make_float2(f.x + v0, f.y + v1);
            }
            if (n1 < NN) {
                float2 f = *reinterpret_cast<const float2*>(feat + (size_t)n1 * DD + cc);
                *reinterpret_cast<float2*>(outp + (size_t)n1 * DD + cc) =
                    make_float2(f.x + v2, f.y + v3);
            }
        }
}

// ============================== host launch =================================
extern "C" void kernel_launch(void* const* d_in, const int* in_sizes, int n_in,
                              void* d_out, int out_size)
{
    const float* feat  = (const float*)d_in[0];
    const int*   f_idx = (const int*)  d_in[1];
    const int*   t_idx = (const int*)  d_in[2];
    const float* msgW0 = (const float*)d_in[3];
    const float* msgb0 = (const float*)d_in[4];
    const float* msgW1 = (const float*)d_in[5];
    const float* msgb1 = (const float*)d_in[6];
    const float* updW0 = (const float*)d_in[7];
    const float* updb0 = (const float*)d_in[8];
    const float* updW1 = (const float*)d_in[9];
    const float* updb1 = (const float*)d_in[10];
    float* out = (float*)d_out;

    cudaFuncSetAttribute(pq_kernel,   cudaFuncAttributeMaxDynamicSharedMemorySize, P_SMEM);
    cudaFuncSetAttribute(edge_kernel, cudaFuncAttributeMaxDynamicSharedMemorySize, E_SMEM);
    cudaFuncSetAttribute(node_kernel, cudaFuncAttributeMaxDynamicSharedMemorySize, N_SMEM);

    conv_w_kernel<<<768, 256>>>(msgW0, updW0, msgW1, updW1);
    zero_agg_kernel<<<1024, 256>>>();

    const int pq_tiles   = (NN + TM - 1) / TM;  // 391
    const int node_tiles = (NN + TM - 1) / TM;  // 391

    pq_kernel<<<pq_tiles, 512, P_SMEM>>>(feat, msgb0, updb0);
    edge_kernel<<<152, 512, E_SMEM>>>(f_idx, t_idx, msgb1);
    node_kernel<<<node_tiles, 512, N_SMEM>>>(feat, updb1, out);
}

// round 14
// speedup vs baseline: 1.1751x; 1.1751x over previous
#include <cuda_runtime.h>
#include <cuda_bf16.h>
#include <cstdint>
#include <cstddef>

#define NN 50000
#define NE 600000
#define DD 128
#define HH 256
#define TM 128

// ============================ device scratch ================================
__device__ float g_agg[(size_t)NN * DD];
__device__ float g_PQ[(size_t)NN * 512];   // per-node [P|Q] for msg MLP
__device__ float g_R[(size_t)NN * HH];     // per-node R = feat@uW0b + updb0
// weights transposed to [N][K] row-major, bf16 hi/lo split
__device__ __nv_bfloat16 g_c0h[512 * DD], g_c0l[512 * DD];   // msg [W0a|W0b]^T : [512][128]
__device__ __nv_bfloat16 g_uah[HH * DD],  g_ual[HH * DD];    // upd W0a^T: [256][128]
__device__ __nv_bfloat16 g_ubh[HH * DD],  g_ubl[HH * DD];    // upd W0b^T: [256][128]
__device__ __nv_bfloat16 g_mW1h[DD * HH], g_mW1l[DD * HH];   // msg W1^T: [128][256]
__device__ __nv_bfloat16 g_uW1h[DD * HH], g_uW1l[DD * HH];   // upd W1^T: [128][256]

// ============================ PTX helpers ===================================
__device__ __forceinline__ uint32_t smem_u32(const void* p) {
    uint32_t a;
    asm("{ .reg .u64 t; cvta.to.shared.u64 t, %1; cvt.u32.u64 %0, t; }" : "=r"(a) : "l"(p));
    return a;
}
__device__ __forceinline__ void ldsm_x4(uint32_t& r0, uint32_t& r1, uint32_t& r2,
                                        uint32_t& r3, uint32_t addr) {
    asm volatile("ldmatrix.sync.aligned.m8n8.x4.shared.b16 {%0,%1,%2,%3}, [%4];"
                 : "=r"(r0), "=r"(r1), "=r"(r2), "=r"(r3) : "r"(addr));
}
__device__ __forceinline__ void mma_bf16(float* d, const uint32_t* a,
                                         uint32_t b0, uint32_t b1) {
    asm volatile(
        "mma.sync.aligned.m16n8k16.row.col.f32.bf16.bf16.f32 "
        "{%0,%1,%2,%3},{%4,%5,%6,%7},{%8,%9},{%0,%1,%2,%3};"
        : "+f"(d[0]), "+f"(d[1]), "+f"(d[2]), "+f"(d[3])
        : "r"(a[0]), "r"(a[1]), "r"(a[2]), "r"(a[3]), "r"(b0), "r"(b1));
}
__device__ __forceinline__ uint32_t pack_bf16(float a, float b) {
    __nv_bfloat162 t = __floats2bfloat162_rn(a, b);
    return *reinterpret_cast<uint32_t*>(&t);
}
__device__ __forceinline__ void cpa16(uint32_t dst, const void* src) {
    asm volatile("cp.async.cg.shared.global [%0], [%1], 16;"
                 :: "r"(dst), "l"(src) : "memory");
}
#define CP_COMMIT() asm volatile("cp.async.commit_group;" ::: "memory")
#define CP_WAIT(n)  asm volatile("cp.async.wait_group %0;" :: "n"(n) : "memory")
__device__ __forceinline__ void red_add2(float* a, float v0, float v1) {
    asm volatile("red.global.add.v2.f32 [%0], {%1, %2};"
                 :: "l"(a), "f"(v0), "f"(v1) : "memory");
}
__device__ __forceinline__ void bar_q(int id) {
    asm volatile("bar.sync %0, 128;" :: "r"(id) : "memory");
}

// store float4 -> hi/lo bf16x2 pairs at byte offset off in two tiles
__device__ __forceinline__ void split_store(char* smc, int hi_base, int lo_base,
                                            int off, float4 v) {
    __nv_bfloat16 h0 = __float2bfloat16(v.x), h1 = __float2bfloat16(v.y);
    __nv_bfloat16 h2 = __float2bfloat16(v.z), h3 = __float2bfloat16(v.w);
    uint2 H, L;
    H.x = pack_bf16(v.x, v.y);
    H.y = pack_bf16(v.z, v.w);
    L.x = pack_bf16(v.x - __bfloat162float(h0), v.y - __bfloat162float(h1));
    L.y = pack_bf16(v.z - __bfloat162float(h2), v.w - __bfloat162float(h3));
    *reinterpret_cast<uint2*>(smc + hi_base + off) = H;
    *reinterpret_cast<uint2*>(smc + lo_base + off) = L;
}

__device__ __forceinline__ float4 relu_add4(float4 p, float4 q) {
    float4 v;
    v.x = fmaxf(p.x + q.x, 0.f);
    v.y = fmaxf(p.y + q.y, 0.f);
    v.z = fmaxf(p.z + q.z, 0.f);
    v.w = fmaxf(p.w + q.w, 0.f);
    return v;
}

// =========================== prelude kernels ================================
__global__ void zero_agg_kernel() {
    const size_t n4 = (size_t)NN * DD / 4;
    float4 z = make_float4(0.f, 0.f, 0.f, 0.f);
    for (size_t i = (size_t)blockIdx.x * blockDim.x + threadIdx.x; i < n4;
         i += (size_t)gridDim.x * blockDim.x)
        reinterpret_cast<float4*>(g_agg)[i] = z;
}

__device__ __forceinline__ void put_split(__nv_bfloat16* h, __nv_bfloat16* l,
                                          int idx, float w) {
    __nv_bfloat16 hi = __float2bfloat16(w);
    h[idx] = hi;
    l[idx] = __float2bfloat16(w - __bfloat162float(hi));
}

__global__ void conv_w_kernel(const float* __restrict__ mW0, const float* __restrict__ uW0,
                              const float* __restrict__ mW1, const float* __restrict__ uW1) {
    int i = blockIdx.x * blockDim.x + threadIdx.x;
    if (i >= 196608) return;
    if (i < 65536) {                      // msg [W0a|W0b]^T
        int n = i >> 7, k = i & 127;
        float w = (n < 256) ? mW0[k * HH + n] : mW0[(128 + k) * HH + (n - 256)];
        put_split(g_c0h, g_c0l, n * DD + k, w);
    } else if (i < 98304) {               // upd W0a^T (agg part)
        int j = i - 65536, n = j >> 7, k = j & 127;
        put_split(g_uah, g_ual, n * DD + k, uW0[k * HH + n]);
    } else if (i < 131072) {              // upd W0b^T (feat part)
        int j = i - 98304, n = j >> 7, k = j & 127;
        put_split(g_ubh, g_ubl, n * DD + k, uW0[(DD + k) * HH + n]);
    } else if (i < 163840) {              // msg W1^T
        int j = i - 131072, k = j >> 7, n = j & 127;
        put_split(g_mW1h, g_mW1l, n * HH + k, mW1[j]);
    } else {                              // upd W1^T
        int j = i - 163840, k = j >> 7, n = j & 127;
        put_split(g_uW1h, g_uW1l, n * HH + k, uW1[j]);
    }
}

// generic B-chunk stager: nrows x 32 K-cols, BROW=80, 512 threads
__device__ __forceinline__ void stage_b(uint32_t bbase, int tid,
                                        const __nv_bfloat16* Wh,
                                        const __nv_bfloat16* Wl,
                                        int row_base, int chunk, int nrows,
                                        int kstride, int bhalf) {
    #pragma unroll
    for (int i = 0; i < 2; ++i) {
        int idx = tid + i * 512;
        if (idx < nrows * 4) {
            int row = idx >> 2, seg = idx & 3;
            uint32_t d = bbase + (uint32_t)(row * 80 + seg * 16);
            const int so = (row_base + row) * kstride + chunk * 32 + seg * 8;
            cpa16(d, Wh + so);
            cpa16(d + bhalf, Wl + so);
        }
    }
}

// ======================= PQ+R precompute kernel =============================
#define P_B0    0
#define P_UB0   1024
#define P_AHI   4096
#define P_ALO   (4096 + 34816)          // 38912
#define P_B     (38912 + 34816)         // 73728
#define P_BHALF 20480
#define P_BBUF  40960
#define P_SMEM  (73728 + 2 * P_BBUF)    // 155648
#define AROW2   272

__global__ void __launch_bounds__(512, 1) pq_kernel(const float* __restrict__ feat,
                                                    const float* __restrict__ b0,
                                                    const float* __restrict__ ub0) {
    extern __shared__ char smc[];
    const uint32_t sb = smem_u32(smc);
    const int tid  = threadIdx.x;
    const int wid  = tid >> 5;
    const int lane = tid & 31;
    const int wr   = wid & 3;
    const int wc   = wid >> 2;
    const int lrow = ((lane >> 3) & 1) * 8 + (lane & 7);
    const int lcol = (lane >> 4) * 8;
    float* b0s  = reinterpret_cast<float*>(smc + P_B0);
    float* ub0s = reinterpret_cast<float*>(smc + P_UB0);

    const int tile0 = blockIdx.x * TM;
    if (tid < 256) b0s[tid] = b0[tid];
    else ub0s[tid - 256] = ub0[tid - 256];

    stage_b(sb + P_B, tid, g_c0h, g_c0l, 0, 0, 256, DD, P_BHALF);
    CP_COMMIT();

    {
        const float4* f4 = reinterpret_cast<const float4*>(feat);
        #pragma unroll
        for (int it = 0; it < 8; ++it) {
            int ci = tid + it * 512;
            int r  = ci >> 5;
            int c4 = ci & 31;
            int node = tile0 + r;
            float4 v = make_float4(0.f, 0.f, 0.f, 0.f);
            if (node < NN) v = f4[(size_t)node * 32 + c4];
            split_store(smc, P_AHI, P_ALO, r * AROW2 + c4 * 8, v);
        }
    }
    __syncthreads();

    for (int h = 0; h < 3; ++h) {
        float acc[2][8][4];
        #pragma unroll
        for (int m = 0; m < 2; ++m)
            #pragma unroll
            for (int n = 0; n < 8; ++n)
                #pragma unroll
                for (int q = 0; q < 4; ++q) acc[m][n][q] = 0.f;

        for (int c = 0; c < 4; ++c) {
            int gg = h * 4 + c;
            if (gg < 11) {
                int gn = gg + 1, hn = gn >> 2, cn = gn & 3;
                const __nv_bfloat16* Wh = (hn < 2) ? g_c0h : g_ubh;
                const __nv_bfloat16* Wl = (hn < 2) ? g_c0l : g_ubl;
                int rb = (hn == 1) ? 256 : 0;
                stage_b(sb + P_B + (uint32_t)(gn & 1) * P_BBUF, tid,
                        Wh, Wl, rb, cn, 256, DD, P_BHALF);
            }
            CP_COMMIT();
            CP_WAIT(1);
            __syncthreads();
            const uint32_t bbase = sb + P_B + (uint32_t)(gg & 1) * P_BBUF;
            #pragma unroll
            for (int ks = 0; ks < 2; ++ks) {
                const int kA = c * 32 + ks * 16;
                uint32_t ah[2][4], al[2][4];
                #pragma unroll
                for (int mt = 0; mt < 2; ++mt) {
                    uint32_t aaddr = sb + P_AHI +
                        (uint32_t)((wr * 32 + mt * 16 + lrow) * AROW2 + (kA + lcol) * 2);
                    ldsm_x4(ah[mt][0], ah[mt][1], ah[mt][2], ah[mt][3], aaddr);
                    ldsm_x4(al[mt][0], al[mt][1], al[mt][2], al[mt][3],
                            aaddr + (P_ALO - P_AHI));
                }
                #pragma unroll
                for (int np = 0; np < 4; ++np) {
                    uint32_t baddr = bbase +
                        (uint32_t)((wc * 64 + np * 16 + lrow) * 80 + (ks * 16 + lcol) * 2);
                    uint32_t bh0, bh1, bh2, bh3, bl0, bl1, bl2, bl3;
                    ldsm_x4(bh0, bh1, bh2, bh3, baddr);
                    ldsm_x4(bl0, bl1, bl2, bl3, baddr + P_BHALF);
                    const int nb = np * 2;
                    #pragma unroll
                    for (int mt = 0; mt < 2; ++mt) {
                        mma_bf16(acc[mt][nb],     ah[mt], bh0, bh2);
                        mma_bf16(acc[mt][nb + 1], ah[mt], bh1, bh3);
                        mma_bf16(acc[mt][nb],     al[mt], bh0, bh2);
                        mma_bf16(acc[mt][nb + 1], al[mt], bh1, bh3);
                        mma_bf16(acc[mt][nb],     ah[mt], bl0, bl2);
                        mma_bf16(acc[mt][nb + 1], ah[mt], bl1, bl3);
                    }
                }
            }
            __syncthreads();
        }

        #pragma unroll
        for (int mt = 0; mt < 2; ++mt)
            #pragma unroll
            for (int nt = 0; nt < 8; ++nt) {
                int cc = wc * 64 + nt * 8 + 2 * (lane & 3);
                int r0 = wr * 32 + mt * 16 + (lane >> 2);
                int r1 = r0 + 8;
                float* d = acc[mt][nt];
                float bb0 = (h == 0) ? b0s[cc]      : (h == 2) ? ub0s[cc]     : 0.f;
                float bb1 = (h == 0) ? b0s[cc + 1]  : (h == 2) ? ub0s[cc + 1] : 0.f;
                int n0 = tile0 + r0, n1 = tile0 + r1;
                if (h < 2) {
                    int co = h * 256 + cc;
                    if (n0 < NN)
                        *reinterpret_cast<float2*>(g_PQ + (size_t)n0 * 512 + co) =
                            make_float2(d[0] + bb0, d[1] + bb1);
                    if (n1 < NN)
                        *reinterpret_cast<float2*>(g_PQ + (size_t)n1 * 512 + co) =
                            make_float2(d[2] + bb0, d[3] + bb1);
                } else {
                    if (n0 < NN)
                        *reinterpret_cast<float2*>(g_R + (size_t)n0 * HH + cc) =
                            make_float2(d[0] + bb0, d[1] + bb1);
                    if (n1 < NN)
                        *reinterpret_cast<float2*>(g_R + (size_t)n1 * HH + cc) =
                            make_float2(d[2] + bb0, d[3] + bb1);
                }
            }
    }
}

// ============== edge kernel (persistent, FOUR independent groups) ===========
// Group g (warps 4g..4g+3, 128 thr) processes its own stream of 32-row edge
// tiles. One warp per SMSP per group -> 4 independently-phased streams per
// scheduler. W1 smem-resident. Bias in registers; next-tile indices prefetched.
#define TME    32                      // edge rows per group-tile
#define E_B1   0                       // 128 floats
#define E_TO   512                     // 8 x 32 ints: [g][parity]
#define E_A    4096                    // per group: 2 bufs of (hi 2560 + lo 2560)
#define E_B    (4096 + 40960)          // 45056; B hi: 8 chunks * 10240; lo at +81920
#define E_SMEM (45056 + 163840)        // 208896

#define EDGE_T32 (NE / TME)            // 18750

__global__ void __launch_bounds__(512, 1) edge_kernel(
    const int* __restrict__ from_idx, const int* __restrict__ to_idx,
    const float* __restrict__ b1)
{
    extern __shared__ char smc[];
    const uint32_t sb = smem_u32(smc);
    const int tid  = threadIdx.x;
    const int wid  = tid >> 5;
    const int lane = tid & 31;
    const int g    = wid >> 2;            // group 0..3
    const int wc   = wid & 3;             // col group 0..3 (32 cols each)
    const int lrow = ((lane >> 3) & 1) * 8 + (lane & 7);
    const int lcol = (lane >> 4) * 8;
    const int barid = 1 + g;

    float* b1s = reinterpret_cast<float*>(smc + E_B1);
    if (tid < 128) b1s[tid] = b1[tid];

    // ---- stage resident W1 hi/lo once ----
    #pragma unroll
    for (int i = 0; i < 8; ++i) {
        int idx = tid + i * 512;          // c*512 + row*4 + seg
        int c = idx >> 9, rs = idx & 511;
        int row = rs >> 2, seg = rs & 3;
        uint32_t d = sb + E_B + (uint32_t)(c * 10240 + row * 80 + seg * 16);
        int so = row * HH + c * 32 + seg * 8;
        cpa16(d, g_mW1h + so);
        cpa16(d + 81920, g_mW1l + so);
    }
    CP_COMMIT();
    CP_WAIT(0);
    __syncthreads();                      // last full-CTA sync

    // hoist bias values into registers (constant across tiles)
    float bv0[4], bv1[4];
    #pragma unroll
    for (int nt = 0; nt < 4; ++nt) {
        int cc = wc * 32 + nt * 8 + 2 * (lane & 3);
        bv0[nt] = b1s[cc];
        bv1[nt] = b1s[cc + 1];
    }

    const float4* pq4 = reinterpret_cast<const float4*>(g_PQ);
    const int ptid = tid & 127;           // group-local thread id
    const int r  = ptid >> 2;             // local row 0..31
    const int sg = ptid & 3;              // seg: 2 float4 per seg
    const int ga = E_A + g * 10240;       // group A buffers

    int tile = blockIdx.x * 4 + g;
    int fr = 0, to = 0;
    if (tile < EDGE_T32) {
        fr = from_idx[tile * TME + r];
        to = to_idx[tile * TME + r];
    }

    int tcnt = 0;
    for (; tile < EDGE_T32; tile += gridDim.x * 4, ++tcnt) {
        int* stob = reinterpret_cast<int*>(smc + E_TO + (g * 2 + (tcnt & 1)) * 128);
        if (sg == 0) stob[r] = to;

        const size_t prow = (size_t)fr * 128 + sg * 2;        // float4 units
        const size_t qrow = (size_t)to * 128 + 64 + sg * 2;

        // produce chunk 0 into buf 0
        {
            float4 p0 = pq4[prow], p1 = pq4[prow + 1];
            float4 q0 = pq4[qrow], q1 = pq4[qrow + 1];
            int off = r * 80 + sg * 16;
            split_store(smc, ga, ga + 2560, off,     relu_add4(p0, q0));
            split_store(smc, ga, ga + 2560, off + 8, relu_add4(p1, q1));
        }
        bar_q(barid);

        // prefetch next tile's indices (latency hidden under 8 MMA chunks)
        int frN = 0, toN = 0;
        {
            int tnext = tile + gridDim.x * 4;
            if (tnext < EDGE_T32) {
                frN = from_idx[tnext * TME + r];
                toN = to_idx[tnext * TME + r];
            }
        }

        float ac2[2][4][4];
        #pragma unroll
        for (int m = 0; m < 2; ++m)
            #pragma unroll
            for (int n = 0; n < 4; ++n)
                #pragma unroll
                for (int q = 0; q < 4; ++q) ac2[m][n][q] = 0.f;

        #pragma unroll
        for (int c = 0; c < 8; ++c) {
            // issue next chunk's gathers (latency hidden by MMA below)
            float4 p0, p1, q0, q1;
            if (c < 7) {
                p0 = pq4[prow + (c + 1) * 8];
                p1 = pq4[prow + (c + 1) * 8 + 1];
                q0 = pq4[qrow + (c + 1) * 8];
                q1 = pq4[qrow + (c + 1) * 8 + 1];
            }
            const uint32_t abase = sb + (uint32_t)(ga + (c & 1) * 5120);
            const uint32_t bbase = sb + E_B + (uint32_t)(c * 10240);
            #pragma unroll
            for (int ks = 0; ks < 2; ++ks) {
                uint32_t ah[2][4], al[2][4];
                #pragma unroll
                for (int mt = 0; mt < 2; ++mt) {
                    uint32_t aaddr = abase +
                        (uint32_t)((mt * 16 + lrow) * 80 + (ks * 16 + lcol) * 2);
                    ldsm_x4(ah[mt][0], ah[mt][1], ah[mt][2], ah[mt][3], aaddr);
                    ldsm_x4(al[mt][0], al[mt][1], al[mt][2], al[mt][3], aaddr + 2560);
                }
                #pragma unroll
                for (int np = 0; np < 2; ++np) {
                    uint32_t baddr = bbase +
                        (uint32_t)((wc * 32 + np * 16 + lrow) * 80 + (ks * 16 + lcol) * 2);
                    uint32_t bh0, bh1, bh2, bh3, bl0, bl1, bl2, bl3;
                    ldsm_x4(bh0, bh1, bh2, bh3, baddr);
                    ldsm_x4(bl0, bl1, bl2, bl3, baddr + 81920);
                    const int nb = np * 2;
                    #pragma unroll
                    for (int mt = 0; mt < 2; ++mt) {
                        mma_bf16(ac2[mt][nb],     ah[mt], bh0, bh2);
                        mma_bf16(ac2[mt][nb + 1], ah[mt], bh1, bh3);
                        mma_bf16(ac2[mt][nb],     al[mt], bh0, bh2);
                        mma_bf16(ac2[mt][nb + 1], al[mt], bh1, bh3);
                        mma_bf16(ac2[mt][nb],     ah[mt], bl0, bl2);
                        mma_bf16(ac2[mt][nb + 1], ah[mt], bl1, bl3);
                    }
                }
            }
            if (c < 7) {
                const int ab = ga + ((c + 1) & 1) * 5120;
                int off = r * 80 + sg * 16;
                split_store(smc, ab, ab + 2560, off,     relu_add4(p0, q0));
                split_store(smc, ab, ab + 2560, off + 8, relu_add4(p1, q1));
            }
            bar_q(barid);
        }

        // ---- epilogue: bias+relu, vectorized red scatter ----
        const int* stor =
            reinterpret_cast<const int*>(smc + E_TO + (g * 2 + (tcnt & 1)) * 128);
        #pragma unroll
        for (int mt = 0; mt < 2; ++mt)
            #pragma unroll
            for (int nt = 0; nt < 4; ++nt) {
                int cc = wc * 32 + nt * 8 + 2 * (lane & 3);
                int r0 = mt * 16 + (lane >> 2);
                int r1 = r0 + 8;
                float* d = ac2[mt][nt];
                float v0 = fmaxf(d[0] + bv0[nt], 0.f), v1 = fmaxf(d[1] + bv1[nt], 0.f);
                float v2 = fmaxf(d[2] + bv0[nt], 0.f), v3 = fmaxf(d[3] + bv1[nt], 0.f);
                red_add2(g_agg + (size_t)stor[r0] * DD + cc, v0, v1);
                red_add2(g_agg + (size_t)stor[r1] * DD + cc, v2, v3);
            }

        fr = frN;
        to = toN;
    }
}

// ============================ node kernel (K-folded) ========================
// S = agg@uW0a (K=128); h = relu(S + R[n]); out = feat + relu(h@uW1 + b1)
#define SM_B1   1024
#define SM_AHI  4096
#define SM_ALO  (4096 + 67584)          // 71680
#define SM_B    (71680 + 67584)         // 139264
#define N_BHALF 20480
#define N_BBUF  40960
#define N_SMEM  (139264 + 2 * N_BBUF)   // 221184
#define AROW 528

__global__ void __launch_bounds__(512, 1) node_kernel(
    const float* __restrict__ feat,
    const float* __restrict__ b1,
    float* __restrict__ outp)
{
    extern __shared__ char smc[];
    const uint32_t sb = smem_u32(smc);
    const int tid  = threadIdx.x;
    const int wid  = tid >> 5;
    const int lane = tid & 31;
    const int wr   = wid & 3;
    const int wc   = wid >> 2;
    const int lrow = ((lane >> 3) & 1) * 8 + (lane & 7);
    const int lcol = (lane >> 4) * 8;

    float* b1s = reinterpret_cast<float*>(smc + SM_B1);

    const int tile0 = blockIdx.x * TM;

    if (tid < 128) b1s[tid] = b1[tid];

    stage_b(sb + SM_B, tid, g_uah, g_ual, 0, 0, 256, DD, N_BHALF);
    CP_COMMIT();
    __syncthreads();

    // gather agg tile [128 x 128]
    {
        const float4* a4 = reinterpret_cast<const float4*>(g_agg);
        #pragma unroll
        for (int it = 0; it < 8; ++it) {
            int ci = tid + it * 512;
            int r  = ci >> 5;
            int c4 = ci & 31;
            int node = tile0 + r;
            float4 v = make_float4(0.f, 0.f, 0.f, 0.f);
            if (node < NN) v = a4[(size_t)node * 32 + c4];
            split_store(smc, SM_AHI, SM_ALO, r * AROW + c4 * 8, v);
        }
    }
    __syncthreads();

    // GEMM1: S = agg@uW0a, K=128 -> 4 chunks
    float acc[2][8][4];
    #pragma unroll
    for (int m = 0; m < 2; ++m)
        #pragma unroll
        for (int n = 0; n < 8; ++n)
            #pragma unroll
            for (int q = 0; q < 4; ++q) acc[m][n][q] = 0.f;

    for (int c = 0; c < 4; ++c) {
        if (c < 3)
            stage_b(sb + SM_B + (uint32_t)((c + 1) & 1) * N_BBUF, tid,
                    g_uah, g_ual, 0, c + 1, 256, DD, N_BHALF);
        CP_COMMIT();
        CP_WAIT(1);
        __syncthreads();
        const uint32_t bbase = sb + SM_B + (uint32_t)(c & 1) * N_BBUF;
        #pragma unroll
        for (int ks = 0; ks < 2; ++ks) {
            const int kA = c * 32 + ks * 16;
            uint32_t ah[2][4], al[2][4];
            #pragma unroll
            for (int mt = 0; mt < 2; ++mt) {
                uint32_t aaddr = sb + SM_AHI +
                    (uint32_t)((wr * 32 + mt * 16 + lrow) * AROW + (kA + lcol) * 2);
                ldsm_x4(ah[mt][0], ah[mt][1], ah[mt][2], ah[mt][3], aaddr);
                ldsm_x4(al[mt][0], al[mt][1], al[mt][2], al[mt][3],
                        aaddr + (SM_ALO - SM_AHI));
            }
            #pragma unroll
            for (int np = 0; np < 4; ++np) {
                uint32_t baddr = bbase +
                    (uint32_t)((wc * 64 + np * 16 + lrow) * 80 + (ks * 16 + lcol) * 2);
                uint32_t bh0, bh1, bh2, bh3, bl0, bl1, bl2, bl3;
                ldsm_x4(bh0, bh1, bh2, bh3, baddr);
                ldsm_x4(bl0, bl1, bl2, bl3, baddr + N_BHALF);
                const int nb = np * 2;
                #pragma unroll
                for (int mt = 0; mt < 2; ++mt) {
                    mma_bf16(acc[mt][nb],     ah[mt], bh0, bh2);
                    mma_bf16(acc[mt][nb + 1], ah[mt], bh1, bh3);
                    mma_bf16(acc[mt][nb],     al[mt], bh0, bh2);
                    mma_bf16(acc[mt][nb + 1], al[mt], bh1, bh3);
                    mma_bf16(acc[mt][nb],     ah[mt], bl0, bl2);
                    mma_bf16(acc[mt][nb + 1], ah[mt], bl1, bl3);
                }
            }
        }
        __syncthreads();
    }

    stage_b(sb + SM_B, tid, g_uW1h, g_uW1l, 0, 0, 128, HH, N_BHALF);
    CP_COMMIT();

    // epilogue1: h = relu(S + R[n]) back into A tiles
    #pragma unroll
    for (int mt = 0; mt < 2; ++mt)
        #pragma unroll
        for (int nt = 0; nt < 8; ++nt) {
            int cc = wc * 64 + nt * 8 + 2 * (lane & 3);
            int r0 = wr * 32 + mt * 16 + (lane >> 2);
            int n0 = tile0 + r0, n1 = n0 + 8;
            float* d = acc[mt][nt];
            float2 R0 = make_float2(0.f, 0.f), R1 = make_float2(0.f, 0.f);
            if (n0 < NN) R0 = *reinterpret_cast<const float2*>(g_R + (size_t)n0 * HH + cc);
            if (n1 < NN) R1 = *reinterpret_cast<const float2*>(g_R + (size_t)n1 * HH + cc);
            float v0 = fmaxf(d[0] + R0.x, 0.f), v1 = fmaxf(d[1] + R0.y, 0.f);
            float v2 = fmaxf(d[2] + R1.x, 0.f), v3 = fmaxf(d[3] + R1.y, 0.f);
            __nv_bfloat16 h0 = __float2bfloat16(v0), h1 = __float2bfloat16(v1);
            __nv_bfloat16 h2 = __float2bfloat16(v2), h3 = __float2bfloat16(v3);
            int o0 = r0 * AROW + cc * 2;
            int o1 = (r0 + 8) * AROW + cc * 2;
            *reinterpret_cast<uint32_t*>(smc + SM_AHI + o0) = pack_bf16(v0, v1);
            *reinterpret_cast<uint32_t*>(smc + SM_AHI + o1) = pack_bf16(v2, v3);
            *reinterpret_cast<uint32_t*>(smc + SM_ALO + o0) =
                pack_bf16(v0 - __bfloat162float(h0), v1 - __bfloat162float(h1));
            *reinterpret_cast<uint32_t*>(smc + SM_ALO + o1) =
                pack_bf16(v2 - __bfloat162float(h2), v3 - __bfloat162float(h3));
        }

    // GEMM2: M = h@uW1, K=256 -> 8 chunks
    float ac2[2][4][4];
    #pragma unroll
    for (int m = 0; m < 2; ++m)
        #pragma unroll
        for (int n = 0; n < 4; ++n)
            #pragma unroll
            for (int q = 0; q < 4; ++q) ac2[m][n][q] = 0.f;

    for (int c = 0; c < 8; ++c) {
        if (c < 7)
            stage_b(sb + SM_B + (uint32_t)((c + 1) & 1) * N_BBUF, tid,
                    g_uW1h, g_uW1l, 0, c + 1, 128, HH, N_BHALF);
        CP_COMMIT();
        CP_WAIT(1);
        __syncthreads();
        const uint32_t bbase = sb + SM_B + (uint32_t)(c & 1) * N_BBUF;
        #pragma unroll
        for (int ks = 0; ks < 2; ++ks) {
            const int kA = c * 32 + ks * 16;
            uint32_t ah[2][4], al[2][4];
            #pragma unroll
            for (int mt = 0; mt < 2; ++mt) {
                uint32_t aaddr = sb + SM_AHI +
                    (uint32_t)((wr * 32 + mt * 16 + lrow) * AROW + (kA + lcol) * 2);
                ldsm_x4(ah[mt][0], ah[mt][1], ah[mt][2], ah[mt][3], aaddr);
                ldsm_x4(al[mt][0], al[mt][1], al[mt][2], al[mt][3],
                        aaddr + (SM_ALO - SM_AHI));
            }
            #pragma unroll
            for (int np = 0; np < 2; ++np) {
                uint32_t baddr = bbase +
                    (uint32_t)((wc * 32 + np * 16 + lrow) * 80 + (ks * 16 + lcol) * 2);
                uint32_t bh0, bh1, bh2, bh3, bl0, bl1, bl2, bl3;
                ldsm_x4(bh0, bh1, bh2, bh3, baddr);
                ldsm_x4(bl0, bl1, bl2, bl3, baddr + N_BHALF);
                const int nb = np * 2;
                #pragma unroll
                for (int mt = 0; mt < 2; ++mt) {
                    mma_bf16(ac2[mt][nb],     ah[mt], bh0, bh2);
                    mma_bf16(ac2[mt][nb + 1], ah[mt], bh1, bh3);
                    mma_bf16(ac2[mt][nb],     al[mt], bh0, bh2);
                    mma_bf16(ac2[mt][nb + 1], al[mt], bh1, bh3);
                    mma_bf16(ac2[mt][nb],     ah[mt], bl0, bl2);
                    mma_bf16(ac2[mt][nb + 1], ah[mt], bl1, bl3);
                }
            }
        }
        __syncthreads();
    }

    // epilogue2: residual store
    #pragma unroll
    for (int mt = 0; mt < 2; ++mt)
        #pragma unroll
        for (int nt = 0; nt < 4; ++nt) {
            int cc = wc * 32 + nt * 8 + 2 * (lane & 3);
            int r0 = wr * 32 + mt * 16 + (lane >> 2);
            int r1 = r0 + 8;
            float* d = ac2[mt][nt];
            float v0 = fmaxf(d[0] + b1s[cc], 0.f), v1 = fmaxf(d[1] + b1s[cc + 1], 0.f);
            float v2 = fmaxf(d[2] + b1s[cc], 0.f), v3 = fmaxf(d[3] + b1s[cc + 1], 0.f);
            int n0 = tile0 + r0, n1 = tile0 + r1;
            if (n0 < NN) {
                float2 f = *reinterpret_cast<const float2*>(feat + (size_t)n0 * DD + cc);
                *reinterpret_cast<float2*>(outp + (size_t)n0 * DD + cc) =
                    make_float2(f.x + v0, f.y + v1);
            }
            if (n1 < NN) {
                float2 f = *reinterpret_cast<const float2*>(feat + (size_t)n1 * DD + cc);
                *reinterpret_cast<float2*>(outp + (size_t)n1 * DD + cc) =
                    make_float2(f.x + v2, f.y + v3);
            }
        }
}

// ============================== host launch =================================
extern "C" void kernel_launch(void* const* d_in, const int* in_sizes, int n_in,
                              void* d_out, int out_size)
{
    const float* feat  = (const float*)d_in[0];
    const int*   f_idx = (const int*)  d_in[1];
    const int*   t_idx = (const int*)  d_in[2];
    const float* msgW0 = (const float*)d_in[3];
    const float* msgb0 = (const float*)d_in[4];
    const float* msgW1 = (const float*)d_in[5];
    const float* msgb1 = (const float*)d_in[6];
    const float* updW0 = (const float*)d_in[7];
    const float* updb0 = (const float*)d_in[8];
    const float* updW1 = (const float*)d_in[9];
    const float* updb1 = (const float*)d_in[10];
    float* out = (float*)d_out;

    cudaFuncSetAttribute(pq_kernel,   cudaFuncAttributeMaxDynamicSharedMemorySize, P_SMEM);
    cudaFuncSetAttribute(edge_kernel, cudaFuncAttributeMaxDynamicSharedMemorySize, E_SMEM);
    cudaFuncSetAttribute(node_kernel, cudaFuncAttributeMaxDynamicSharedMemorySize, N_SMEM);

    conv_w_kernel<<<768, 256>>>(msgW0, updW0, msgW1, updW1);
    zero_agg_kernel<<<1024, 256>>>();

    const int pq_tiles   = (NN + TM - 1) / TM;  // 391
    const int node_tiles = (NN + TM - 1) / TM;  // 391

    pq_kernel<<<pq_tiles, 512, P_SMEM>>>(feat, msgb0, updb0);
    edge_kernel<<<152, 512, E_SMEM>>>(f_idx, t_idx, msgb1);
    node_kernel<<<node_tiles, 512, N_SMEM>>>(feat, updb1, out);
}

// round 15
// speedup vs baseline: 1.3306x; 1.1324x over previous
#include <cuda_runtime.h>
#include <cuda_bf16.h>
#include <cuda_fp16.h>
#include <cstdint>
#include <cstddef>

#define NN 50000
#define NE 600000
#define DD 128
#define HH 256
#define TM 128

// ============================ device scratch ================================
__device__ float g_agg[(size_t)NN * DD];
__device__ float g_PQ[(size_t)NN * 512];   // per-node [P|Q] for msg MLP
__device__ float g_R[(size_t)NN * HH];     // per-node R = feat@uW0b + updb0
// weights transposed to [N][K] row-major
__device__ __nv_bfloat16 g_c0h[512 * DD], g_c0l[512 * DD];   // msg [W0a|W0b]^T (bf16 hi/lo)
__device__ __nv_bfloat16 g_uah[HH * DD],  g_ual[HH * DD];    // upd W0a^T (bf16 hi/lo)
__device__ __nv_bfloat16 g_ubh[HH * DD],  g_ubl[HH * DD];    // upd W0b^T (bf16 hi/lo)
__device__ __half        g_mW1f[DD * HH];                    // msg W1^T (fp16 single)
__device__ __nv_bfloat16 g_uW1h[DD * HH], g_uW1l[DD * HH];   // upd W1^T (bf16 hi/lo)

// ============================ PTX helpers ===================================
__device__ __forceinline__ uint32_t smem_u32(const void* p) {
    uint32_t a;
    asm("{ .reg .u64 t; cvta.to.shared.u64 t, %1; cvt.u32.u64 %0, t; }" : "=r"(a) : "l"(p));
    return a;
}
__device__ __forceinline__ void ldsm_x4(uint32_t& r0, uint32_t& r1, uint32_t& r2,
                                        uint32_t& r3, uint32_t addr) {
    asm volatile("ldmatrix.sync.aligned.m8n8.x4.shared.b16 {%0,%1,%2,%3}, [%4];"
                 : "=r"(r0), "=r"(r1), "=r"(r2), "=r"(r3) : "r"(addr));
}
__device__ __forceinline__ void mma_bf16(float* d, const uint32_t* a,
                                         uint32_t b0, uint32_t b1) {
    asm volatile(
        "mma.sync.aligned.m16n8k16.row.col.f32.bf16.bf16.f32 "
        "{%0,%1,%2,%3},{%4,%5,%6,%7},{%8,%9},{%0,%1,%2,%3};"
        : "+f"(d[0]), "+f"(d[1]), "+f"(d[2]), "+f"(d[3])
        : "r"(a[0]), "r"(a[1]), "r"(a[2]), "r"(a[3]), "r"(b0), "r"(b1));
}
__device__ __forceinline__ void mma_f16(float* d, const uint32_t* a,
                                        uint32_t b0, uint32_t b1) {
    asm volatile(
        "mma.sync.aligned.m16n8k16.row.col.f32.f16.f16.f32 "
        "{%0,%1,%2,%3},{%4,%5,%6,%7},{%8,%9},{%0,%1,%2,%3};"
        : "+f"(d[0]), "+f"(d[1]), "+f"(d[2]), "+f"(d[3])
        : "r"(a[0]), "r"(a[1]), "r"(a[2]), "r"(a[3]), "r"(b0), "r"(b1));
}
__device__ __forceinline__ uint32_t pack_bf16(float a, float b) {
    __nv_bfloat162 t = __floats2bfloat162_rn(a, b);
    return *reinterpret_cast<uint32_t*>(&t);
}
__device__ __forceinline__ uint32_t pack_f16(float a, float b) {
    __half2 t = __floats2half2_rn(a, b);
    return *reinterpret_cast<uint32_t*>(&t);
}
__device__ __forceinline__ void cpa16(uint32_t dst, const void* src) {
    asm volatile("cp.async.cg.shared.global [%0], [%1], 16;"
                 :: "r"(dst), "l"(src) : "memory");
}
#define CP_COMMIT() asm volatile("cp.async.commit_group;" ::: "memory")
#define CP_WAIT(n)  asm volatile("cp.async.wait_group %0;" :: "n"(n) : "memory")
__device__ __forceinline__ void red_add2(float* a, float v0, float v1) {
    asm volatile("red.global.add.v2.f32 [%0], {%1, %2};"
                 :: "l"(a), "f"(v0), "f"(v1) : "memory");
}
__device__ __forceinline__ void bar_q(int id) {
    asm volatile("bar.sync %0, 128;" :: "r"(id) : "memory");
}

// store float4 -> hi/lo bf16x2 pairs at byte offset off in two tiles
__device__ __forceinline__ void split_store(char* smc, int hi_base, int lo_base,
                                            int off, float4 v) {
    __nv_bfloat16 h0 = __float2bfloat16(v.x), h1 = __float2bfloat16(v.y);
    __nv_bfloat16 h2 = __float2bfloat16(v.z), h3 = __float2bfloat16(v.w);
    uint2 H, L;
    H.x = pack_bf16(v.x, v.y);
    H.y = pack_bf16(v.z, v.w);
    L.x = pack_bf16(v.x - __bfloat162float(h0), v.y - __bfloat162float(h1));
    L.y = pack_bf16(v.z - __bfloat162float(h2), v.w - __bfloat162float(h3));
    *reinterpret_cast<uint2*>(smc + hi_base + off) = H;
    *reinterpret_cast<uint2*>(smc + lo_base + off) = L;
}

// fp16 variant (edge A tiles)
__device__ __forceinline__ void split_store_h(char* smc, int hi_base, int lo_base,
                                              int off, float4 v) {
    __half h0 = __float2half_rn(v.x), h1 = __float2half_rn(v.y);
    __half h2 = __float2half_rn(v.z), h3 = __float2half_rn(v.w);
    uint2 H, L;
    H.x = pack_f16(v.x, v.y);
    H.y = pack_f16(v.z, v.w);
    L.x = pack_f16(v.x - __half2float(h0), v.y - __half2float(h1));
    L.y = pack_f16(v.z - __half2float(h2), v.w - __half2float(h3));
    *reinterpret_cast<uint2*>(smc + hi_base + off) = H;
    *reinterpret_cast<uint2*>(smc + lo_base + off) = L;
}

__device__ __forceinline__ float4 relu_add4(float4 p, float4 q) {
    float4 v;
    v.x = fmaxf(p.x + q.x, 0.f);
    v.y = fmaxf(p.y + q.y, 0.f);
    v.z = fmaxf(p.z + q.z, 0.f);
    v.w = fmaxf(p.w + q.w, 0.f);
    return v;
}

// =========================== prelude kernels ================================
__global__ void zero_agg_kernel() {
    const size_t n4 = (size_t)NN * DD / 4;
    float4 z = make_float4(0.f, 0.f, 0.f, 0.f);
    for (size_t i = (size_t)blockIdx.x * blockDim.x + threadIdx.x; i < n4;
         i += (size_t)gridDim.x * blockDim.x)
        reinterpret_cast<float4*>(g_agg)[i] = z;
}

__device__ __forceinline__ void put_split(__nv_bfloat16* h, __nv_bfloat16* l,
                                          int idx, float w) {
    __nv_bfloat16 hi = __float2bfloat16(w);
    h[idx] = hi;
    l[idx] = __float2bfloat16(w - __bfloat162float(hi));
}

__global__ void conv_w_kernel(const float* __restrict__ mW0, const float* __restrict__ uW0,
                              const float* __restrict__ mW1, const float* __restrict__ uW1) {
    int i = blockIdx.x * blockDim.x + threadIdx.x;
    if (i >= 196608) return;
    if (i < 65536) {                      // msg [W0a|W0b]^T
        int n = i >> 7, k = i & 127;
        float w = (n < 256) ? mW0[k * HH + n] : mW0[(128 + k) * HH + (n - 256)];
        put_split(g_c0h, g_c0l, n * DD + k, w);
    } else if (i < 98304) {               // upd W0a^T (agg part)
        int j = i - 65536, n = j >> 7, k = j & 127;
        put_split(g_uah, g_ual, n * DD + k, uW0[k * HH + n]);
    } else if (i < 131072) {              // upd W0b^T (feat part)
        int j = i - 98304, n = j >> 7, k = j & 127;
        put_split(g_ubh, g_ubl, n * DD + k, uW0[(DD + k) * HH + n]);
    } else if (i < 163840) {              // msg W1^T -> fp16 single
        int j = i - 131072, k = j >> 7, n = j & 127;
        g_mW1f[n * HH + k] = __float2half_rn(mW1[j]);
    } else {                              // upd W1^T
        int j = i - 163840, k = j >> 7, n = j & 127;
        put_split(g_uW1h, g_uW1l, n * HH + k, uW1[j]);
    }
}

// generic B-chunk stager: nrows x 32 K-cols, BROW=80, 512 threads (bf16 hi/lo)
__device__ __forceinline__ void stage_b(uint32_t bbase, int tid,
                                        const __nv_bfloat16* Wh,
                                        const __nv_bfloat16* Wl,
                                        int row_base, int chunk, int nrows,
                                        int kstride, int bhalf) {
    #pragma unroll
    for (int i = 0; i < 2; ++i) {
        int idx = tid + i * 512;
        if (idx < nrows * 4) {
            int row = idx >> 2, seg = idx & 3;
            uint32_t d = bbase + (uint32_t)(row * 80 + seg * 16);
            const int so = (row_base + row) * kstride + chunk * 32 + seg * 8;
            cpa16(d, Wh + so);
            cpa16(d + bhalf, Wl + so);
        }
    }
}

// ======================= PQ+R precompute kernel =============================
#define P_B0    0
#define P_UB0   1024
#define P_AHI   4096
#define P_ALO   (4096 + 34816)          // 38912
#define P_B     (38912 + 34816)         // 73728
#define P_BHALF 20480
#define P_BBUF  40960
#define P_SMEM  (73728 + 2 * P_BBUF)    // 155648
#define AROW2   272

__global__ void __launch_bounds__(512, 1) pq_kernel(const float* __restrict__ feat,
                                                    const float* __restrict__ b0,
                                                    const float* __restrict__ ub0) {
    extern __shared__ char smc[];
    const uint32_t sb = smem_u32(smc);
    const int tid  = threadIdx.x;
    const int wid  = tid >> 5;
    const int lane = tid & 31;
    const int wr   = wid & 3;
    const int wc   = wid >> 2;
    const int lrow = ((lane >> 3) & 1) * 8 + (lane & 7);
    const int lcol = (lane >> 4) * 8;
    float* b0s  = reinterpret_cast<float*>(smc + P_B0);
    float* ub0s = reinterpret_cast<float*>(smc + P_UB0);

    const int tile0 = blockIdx.x * TM;
    if (tid < 256) b0s[tid] = b0[tid];
    else ub0s[tid - 256] = ub0[tid - 256];

    stage_b(sb + P_B, tid, g_c0h, g_c0l, 0, 0, 256, DD, P_BHALF);
    CP_COMMIT();

    {
        const float4* f4 = reinterpret_cast<const float4*>(feat);
        #pragma unroll
        for (int it = 0; it < 8; ++it) {
            int ci = tid + it * 512;
            int r  = ci >> 5;
            int c4 = ci & 31;
            int node = tile0 + r;
            float4 v = make_float4(0.f, 0.f, 0.f, 0.f);
            if (node < NN) v = f4[(size_t)node * 32 + c4];
            split_store(smc, P_AHI, P_ALO, r * AROW2 + c4 * 8, v);
        }
    }
    __syncthreads();

    for (int h = 0; h < 3; ++h) {
        float acc[2][8][4];
        #pragma unroll
        for (int m = 0; m < 2; ++m)
            #pragma unroll
            for (int n = 0; n < 8; ++n)
                #pragma unroll
                for (int q = 0; q < 4; ++q) acc[m][n][q] = 0.f;

        for (int c = 0; c < 4; ++c) {
            int gg = h * 4 + c;
            if (gg < 11) {
                int gn = gg + 1, hn = gn >> 2, cn = gn & 3;
                const __nv_bfloat16* Wh = (hn < 2) ? g_c0h : g_ubh;
                const __nv_bfloat16* Wl = (hn < 2) ? g_c0l : g_ubl;
                int rb = (hn == 1) ? 256 : 0;
                stage_b(sb + P_B + (uint32_t)(gn & 1) * P_BBUF, tid,
                        Wh, Wl, rb, cn, 256, DD, P_BHALF);
            }
            CP_COMMIT();
            CP_WAIT(1);
            __syncthreads();
            const uint32_t bbase = sb + P_B + (uint32_t)(gg & 1) * P_BBUF;
            #pragma unroll
            for (int ks = 0; ks < 2; ++ks) {
                const int kA = c * 32 + ks * 16;
                uint32_t ah[2][4], al[2][4];
                #pragma unroll
                for (int mt = 0; mt < 2; ++mt) {
                    uint32_t aaddr = sb + P_AHI +
                        (uint32_t)((wr * 32 + mt * 16 + lrow) * AROW2 + (kA + lcol) * 2);
                    ldsm_x4(ah[mt][0], ah[mt][1], ah[mt][2], ah[mt][3], aaddr);
                    ldsm_x4(al[mt][0], al[mt][1], al[mt][2], al[mt][3],
                            aaddr + (P_ALO - P_AHI));
                }
                #pragma unroll
                for (int np = 0; np < 4; ++np) {
                    uint32_t baddr = bbase +
                        (uint32_t)((wc * 64 + np * 16 + lrow) * 80 + (ks * 16 + lcol) * 2);
                    uint32_t bh0, bh1, bh2, bh3, bl0, bl1, bl2, bl3;
                    ldsm_x4(bh0, bh1, bh2, bh3, baddr);
                    ldsm_x4(bl0, bl1, bl2, bl3, baddr + P_BHALF);
                    const int nb = np * 2;
                    #pragma unroll
                    for (int mt = 0; mt < 2; ++mt) {
                        mma_bf16(acc[mt][nb],     ah[mt], bh0, bh2);
                        mma_bf16(acc[mt][nb + 1], ah[mt], bh1, bh3);
                        mma_bf16(acc[mt][nb],     al[mt], bh0, bh2);
                        mma_bf16(acc[mt][nb + 1], al[mt], bh1, bh3);
                        mma_bf16(acc[mt][nb],     ah[mt], bl0, bl2);
                        mma_bf16(acc[mt][nb + 1], ah[mt], bl1, bl3);
                    }
                }
            }
            __syncthreads();
        }

        #pragma unroll
        for (int mt = 0; mt < 2; ++mt)
            #pragma unroll
            for (int nt = 0; nt < 8; ++nt) {
                int cc = wc * 64 + nt * 8 + 2 * (lane & 3);
                int r0 = wr * 32 + mt * 16 + (lane >> 2);
                int r1 = r0 + 8;
                float* d = acc[mt][nt];
                float bb0 = (h == 0) ? b0s[cc]      : (h == 2) ? ub0s[cc]     : 0.f;
                float bb1 = (h == 0) ? b0s[cc + 1]  : (h == 2) ? ub0s[cc + 1] : 0.f;
                int n0 = tile0 + r0, n1 = tile0 + r1;
                if (h < 2) {
                    int co = h * 256 + cc;
                    if (n0 < NN)
                        *reinterpret_cast<float2*>(g_PQ + (size_t)n0 * 512 + co) =
                            make_float2(d[0] + bb0, d[1] + bb1);
                    if (n1 < NN)
                        *reinterpret_cast<float2*>(g_PQ + (size_t)n1 * 512 + co) =
                            make_float2(d[2] + bb0, d[3] + bb1);
                } else {
                    if (n0 < NN)
                        *reinterpret_cast<float2*>(g_R + (size_t)n0 * HH + cc) =
                            make_float2(d[0] + bb0, d[1] + bb1);
                    if (n1 < NN)
                        *reinterpret_cast<float2*>(g_R + (size_t)n1 * HH + cc) =
                            make_float2(d[2] + bb0, d[3] + bb1);
                }
            }
    }
}

// ============== edge kernel (persistent, FOUR independent groups) ===========
// fp16 2-pass: H split fp16 hi/lo (A), W1 single fp16 (B) -> 16 MMA, 6 LDSM
// per K16 per warp (vs 24/8 for 3-pass bf16). W1 resident = 80 KB.
#define TME    32                      // edge rows per group-tile
#define E_B1   0                       // 128 floats
#define E_TO   512                     // 8 x 32 ints: [g][parity]
#define E_A    4096                    // per group: 2 bufs of (hi 2560 + lo 2560)
#define E_B    (4096 + 40960)          // 45056; B: 8 chunks * 10240 (fp16, no lo)
#define E_SMEM (45056 + 81920)         // 126976

#define EDGE_T32 (NE / TME)            // 18750

__global__ void __launch_bounds__(512, 1) edge_kernel(
    const int* __restrict__ from_idx, const int* __restrict__ to_idx,
    const float* __restrict__ b1)
{
    extern __shared__ char smc[];
    const uint32_t sb = smem_u32(smc);
    const int tid  = threadIdx.x;
    const int wid  = tid >> 5;
    const int lane = tid & 31;
    const int g    = wid >> 2;            // group 0..3
    const int wc   = wid & 3;             // col group 0..3 (32 cols each)
    const int lrow = ((lane >> 3) & 1) * 8 + (lane & 7);
    const int lcol = (lane >> 4) * 8;
    const int barid = 1 + g;

    float* b1s = reinterpret_cast<float*>(smc + E_B1);
    if (tid < 128) b1s[tid] = b1[tid];

    // ---- stage resident W1 (fp16) once ----
    #pragma unroll
    for (int i = 0; i < 8; ++i) {
        int idx = tid + i * 512;          // c*512 + row*4 + seg
        int c = idx >> 9, rs = idx & 511;
        int row = rs >> 2, seg = rs & 3;
        uint32_t d = sb + E_B + (uint32_t)(c * 10240 + row * 80 + seg * 16);
        cpa16(d, g_mW1f + row * HH + c * 32 + seg * 8);
    }
    CP_COMMIT();
    CP_WAIT(0);
    __syncthreads();                      // last full-CTA sync

    // hoist bias values into registers (constant across tiles)
    float bv0[4], bv1[4];
    #pragma unroll
    for (int nt = 0; nt < 4; ++nt) {
        int cc = wc * 32 + nt * 8 + 2 * (lane & 3);
        bv0[nt] = b1s[cc];
        bv1[nt] = b1s[cc + 1];
    }

    const float4* pq4 = reinterpret_cast<const float4*>(g_PQ);
    const int ptid = tid & 127;           // group-local thread id
    const int r  = ptid >> 2;             // local row 0..31
    const int sg = ptid & 3;              // seg: 2 float4 per seg
    const int ga = E_A + g * 10240;       // group A buffers

    int tile = blockIdx.x * 4 + g;
    int fr = 0, to = 0;
    if (tile < EDGE_T32) {
        fr = from_idx[tile * TME + r];
        to = to_idx[tile * TME + r];
    }

    int tcnt = 0;
    for (; tile < EDGE_T32; tile += gridDim.x * 4, ++tcnt) {
        int* stob = reinterpret_cast<int*>(smc + E_TO + (g * 2 + (tcnt & 1)) * 128);
        if (sg == 0) stob[r] = to;

        const size_t prow = (size_t)fr * 128 + sg * 2;        // float4 units
        const size_t qrow = (size_t)to * 128 + 64 + sg * 2;

        // produce chunk 0 into buf 0
        {
            float4 p0 = pq4[prow], p1 = pq4[prow + 1];
            float4 q0 = pq4[qrow], q1 = pq4[qrow + 1];
            int off = r * 80 + sg * 16;
            split_store_h(smc, ga, ga + 2560, off,     relu_add4(p0, q0));
            split_store_h(smc, ga, ga + 2560, off + 8, relu_add4(p1, q1));
        }
        bar_q(barid);

        // prefetch next tile's indices (latency hidden under 8 MMA chunks)
        int frN = 0, toN = 0;
        {
            int tnext = tile + gridDim.x * 4;
            if (tnext < EDGE_T32) {
                frN = from_idx[tnext * TME + r];
                toN = to_idx[tnext * TME + r];
            }
        }

        float ac2[2][4][4];
        #pragma unroll
        for (int m = 0; m < 2; ++m)
            #pragma unroll
            for (int n = 0; n < 4; ++n)
                #pragma unroll
                for (int q = 0; q < 4; ++q) ac2[m][n][q] = 0.f;

        #pragma unroll
        for (int c = 0; c < 8; ++c) {
            // issue next chunk's gathers (latency hidden by MMA below)
            float4 p0, p1, q0, q1;
            if (c < 7) {
                p0 = pq4[prow + (c + 1) * 8];
                p1 = pq4[prow + (c + 1) * 8 + 1];
                q0 = pq4[qrow + (c + 1) * 8];
                q1 = pq4[qrow + (c + 1) * 8 + 1];
            }
            const uint32_t abase = sb + (uint32_t)(ga + (c & 1) * 5120);
            const uint32_t bbase = sb + E_B + (uint32_t)(c * 10240);
            #pragma unroll
            for (int ks = 0; ks < 2; ++ks) {
                uint32_t ah[2][4], al[2][4];
                #pragma unroll
                for (int mt = 0; mt < 2; ++mt) {
                    uint32_t aaddr = abase +
                        (uint32_t)((mt * 16 + lrow) * 80 + (ks * 16 + lcol) * 2);
                    ldsm_x4(ah[mt][0], ah[mt][1], ah[mt][2], ah[mt][3], aaddr);
                    ldsm_x4(al[mt][0], al[mt][1], al[mt][2], al[mt][3], aaddr + 2560);
                }
                #pragma unroll
                for (int np = 0; np < 2; ++np) {
                    uint32_t baddr = bbase +
                        (uint32_t)((wc * 32 + np * 16 + lrow) * 80 + (ks * 16 + lcol) * 2);
                    uint32_t bh0, bh1, bh2, bh3;
                    ldsm_x4(bh0, bh1, bh2, bh3, baddr);
                    const int nb = np * 2;
                    #pragma unroll
                    for (int mt = 0; mt < 2; ++mt) {
                        mma_f16(ac2[mt][nb],     ah[mt], bh0, bh2);
                        mma_f16(ac2[mt][nb + 1], ah[mt], bh1, bh3);
                        mma_f16(ac2[mt][nb],     al[mt], bh0, bh2);
                        mma_f16(ac2[mt][nb + 1], al[mt], bh1, bh3);
                    }
                }
            }
            if (c < 7) {
                const int ab = ga + ((c + 1) & 1) * 5120;
                int off = r * 80 + sg * 16;
                split_store_h(smc, ab, ab + 2560, off,     relu_add4(p0, q0));
                split_store_h(smc, ab, ab + 2560, off + 8, relu_add4(p1, q1));
            }
            bar_q(barid);
        }

        // ---- epilogue: bias+relu, vectorized red scatter ----
        const int* stor =
            reinterpret_cast<const int*>(smc + E_TO + (g * 2 + (tcnt & 1)) * 128);
        #pragma unroll
        for (int mt = 0; mt < 2; ++mt)
            #pragma unroll
            for (int nt = 0; nt < 4; ++nt) {
                int cc = wc * 32 + nt * 8 + 2 * (lane & 3);
                int r0 = mt * 16 + (lane >> 2);
                int r1 = r0 + 8;
                float* d = ac2[mt][nt];
                float v0 = fmaxf(d[0] + bv0[nt], 0.f), v1 = fmaxf(d[1] + bv1[nt], 0.f);
                float v2 = fmaxf(d[2] + bv0[nt], 0.f), v3 = fmaxf(d[3] + bv1[nt], 0.f);
                red_add2(g_agg + (size_t)stor[r0] * DD + cc, v0, v1);
                red_add2(g_agg + (size_t)stor[r1] * DD + cc, v2, v3);
            }

        fr = frN;
        to = toN;
    }
}

// ============================ node kernel (K-folded) ========================
// S = agg@uW0a (K=128); h = relu(S + R[n]); out = feat + relu(h@uW1 + b1)
#define SM_B1   1024
#define SM_AHI  4096
#define SM_ALO  (4096 + 67584)          // 71680
#define SM_B    (71680 + 67584)         // 139264
#define N_BHALF 20480
#define N_BBUF  40960
#define N_SMEM  (139264 + 2 * N_BBUF)   // 221184
#define AROW 528

__global__ void __launch_bounds__(512, 1) node_kernel(
    const float* __restrict__ feat,
    const float* __restrict__ b1,
    float* __restrict__ outp)
{
    extern __shared__ char smc[];
    const uint32_t sb = smem_u32(smc);
    const int tid  = threadIdx.x;
    const int wid  = tid >> 5;
    const int lane = tid & 31;
    const int wr   = wid & 3;
    const int wc   = wid >> 2;
    const int lrow = ((lane >> 3) & 1) * 8 + (lane & 7);
    const int lcol = (lane >> 4) * 8;

    float* b1s = reinterpret_cast<float*>(smc + SM_B1);

    const int tile0 = blockIdx.x * TM;

    if (tid < 128) b1s[tid] = b1[tid];

    stage_b(sb + SM_B, tid, g_uah, g_ual, 0, 0, 256, DD, N_BHALF);
    CP_COMMIT();
    __syncthreads();

    // gather agg tile [128 x 128]
    {
        const float4* a4 = reinterpret_cast<const float4*>(g_agg);
        #pragma unroll
        for (int it = 0; it < 8; ++it) {
            int ci = tid + it * 512;
            int r  = ci >> 5;
            int c4 = ci & 31;
            int node = tile0 + r;
            float4 v = make_float4(0.f, 0.f, 0.f, 0.f);
            if (node < NN) v = a4[(size_t)node * 32 + c4];
            split_store(smc, SM_AHI, SM_ALO, r * AROW + c4 * 8, v);
        }
    }
    __syncthreads();

    // GEMM1: S = agg@uW0a, K=128 -> 4 chunks
    float acc[2][8][4];
    #pragma unroll
    for (int m = 0; m < 2; ++m)
        #pragma unroll
        for (int n = 0; n < 8; ++n)
            #pragma unroll
            for (int q = 0; q < 4; ++q) acc[m][n][q] = 0.f;

    for (int c = 0; c < 4; ++c) {
        if (c < 3)
            stage_b(sb + SM_B + (uint32_t)((c + 1) & 1) * N_BBUF, tid,
                    g_uah, g_ual, 0, c + 1, 256, DD, N_BHALF);
        CP_COMMIT();
        CP_WAIT(1);
        __syncthreads();
        const uint32_t bbase = sb + SM_B + (uint32_t)(c & 1) * N_BBUF;
        #pragma unroll
        for (int ks = 0; ks < 2; ++ks) {
            const int kA = c * 32 + ks * 16;
            uint32_t ah[2][4], al[2][4];
            #pragma unroll
            for (int mt = 0; mt < 2; ++mt) {
                uint32_t aaddr = sb + SM_AHI +
                    (uint32_t)((wr * 32 + mt * 16 + lrow) * AROW + (kA + lcol) * 2);
                ldsm_x4(ah[mt][0], ah[mt][1], ah[mt][2], ah[mt][3], aaddr);
                ldsm_x4(al[mt][0], al[mt][1], al[mt][2], al[mt][3],
                        aaddr + (SM_ALO - SM_AHI));
            }
            #pragma unroll
            for (int np = 0; np < 4; ++np) {
                uint32_t baddr = bbase +
                    (uint32_t)((wc * 64 + np * 16 + lrow) * 80 + (ks * 16 + lcol) * 2);
                uint32_t bh0, bh1, bh2, bh3, bl0, bl1, bl2, bl3;
                ldsm_x4(bh0, bh1, bh2, bh3, baddr);
                ldsm_x4(bl0, bl1, bl2, bl3, baddr + N_BHALF);
                const int nb = np * 2;
                #pragma unroll
                for (int mt = 0; mt < 2; ++mt) {
                    mma_bf16(acc[mt][nb],     ah[mt], bh0, bh2);
                    mma_bf16(acc[mt][nb + 1], ah[mt], bh1, bh3);
                    mma_bf16(acc[mt][nb],     al[mt], bh0, bh2);
                    mma_bf16(acc[mt][nb + 1], al[mt], bh1, bh3);
                    mma_bf16(acc[mt][nb],     ah[mt], bl0, bl2);
                    mma_bf16(acc[mt][nb + 1], ah[mt], bl1, bl3);
                }
            }
        }
        __syncthreads();
    }

    stage_b(sb + SM_B, tid, g_uW1h, g_uW1l, 0, 0, 128, HH, N_BHALF);
    CP_COMMIT();

    // epilogue1: h = relu(S + R[n]) back into A tiles
    #pragma unroll
    for (int mt = 0; mt < 2; ++mt)
        #pragma unroll
        for (int nt = 0; nt < 8; ++nt) {
            int cc = wc * 64 + nt * 8 + 2 * (lane & 3);
            int r0 = wr * 32 + mt * 16 + (lane >> 2);
            int n0 = tile0 + r0, n1 = n0 + 8;
            float* d = acc[mt][nt];
            float2 R0 = make_float2(0.f, 0.f), R1 = make_float2(0.f, 0.f);
            if (n0 < NN) R0 = *reinterpret_cast<const float2*>(g_R + (size_t)n0 * HH + cc);
            if (n1 < NN) R1 = *reinterpret_cast<const float2*>(g_R + (size_t)n1 * HH + cc);
            float v0 = fmaxf(d[0] + R0.x, 0.f), v1 = fmaxf(d[1] + R0.y, 0.f);
            float v2 = fmaxf(d[2] + R1.x, 0.f), v3 = fmaxf(d[3] + R1.y, 0.f);
            __nv_bfloat16 h0 = __float2bfloat16(v0), h1 = __float2bfloat16(v1);
            __nv_bfloat16 h2 = __float2bfloat16(v2), h3 = __float2bfloat16(v3);
            int o0 = r0 * AROW + cc * 2;
            int o1 = (r0 + 8) * AROW + cc * 2;
            *reinterpret_cast<uint32_t*>(smc + SM_AHI + o0) = pack_bf16(v0, v1);
            *reinterpret_cast<uint32_t*>(smc + SM_AHI + o1) = pack_bf16(v2, v3);
            *reinterpret_cast<uint32_t*>(smc + SM_ALO + o0) =
                pack_bf16(v0 - __bfloat162float(h0), v1 - __bfloat162float(h1));
            *reinterpret_cast<uint32_t*>(smc + SM_ALO + o1) =
                pack_bf16(v2 - __bfloat162float(h2), v3 - __bfloat162float(h3));
        }

    // GEMM2: M = h@uW1, K=256 -> 8 chunks
    float ac2[2][4][4];
    #pragma unroll
    for (int m = 0; m < 2; ++m)
        #pragma unroll
        for (int n = 0; n < 4; ++n)
            #pragma unroll
            for (int q = 0; q < 4; ++q) ac2[m][n][q] = 0.f;

    for (int c = 0; c < 8; ++c) {
        if (c < 7)
            stage_b(sb + SM_B + (uint32_t)((c + 1) & 1) * N_BBUF, tid,
                    g_uW1h, g_uW1l, 0, c + 1, 128, HH, N_BHALF);
        CP_COMMIT();
        CP_WAIT(1);
        __syncthreads();
        const uint32_t bbase = sb + SM_B + (uint32_t)(c & 1) * N_BBUF;
        #pragma unroll
        for (int ks = 0; ks < 2; ++ks) {
            const int kA = c * 32 + ks * 16;
            uint32_t ah[2][4], al[2][4];
            #pragma unroll
            for (int mt = 0; mt < 2; ++mt) {
                uint32_t aaddr = sb + SM_AHI +
                    (uint32_t)((wr * 32 + mt * 16 + lrow) * AROW + (kA + lcol) * 2);
                ldsm_x4(ah[mt][0], ah[mt][1], ah[mt][2], ah[mt][3], aaddr);
                ldsm_x4(al[mt][0], al[mt][1], al[mt][2], al[mt][3],
                        aaddr + (SM_ALO - SM_AHI));
            }
            #pragma unroll
            for (int np = 0; np < 2; ++np) {
                uint32_t baddr = bbase +
                    (uint32_t)((wc * 32 + np * 16 + lrow) * 80 + (ks * 16 + lcol) * 2);
                uint32_t bh0, bh1, bh2, bh3, bl0, bl1, bl2, bl3;
                ldsm_x4(bh0, bh1, bh2, bh3, baddr);
                ldsm_x4(bl0, bl1, bl2, bl3, baddr + N_BHALF);
                const int nb = np * 2;
                #pragma unroll
                for (int mt = 0; mt < 2; ++mt) {
                    mma_bf16(ac2[mt][nb],     ah[mt], bh0, bh2);
                    mma_bf16(ac2[mt][nb + 1], ah[mt], bh1, bh3);
                    mma_bf16(ac2[mt][nb],     al[mt], bh0, bh2);
                    mma_bf16(ac2[mt][nb + 1], al[mt], bh1, bh3);
                    mma_bf16(ac2[mt][nb],     ah[mt], bl0, bl2);
                    mma_bf16(ac2[mt][nb + 1], ah[mt], bl1, bl3);
                }
            }
        }
        __syncthreads();
    }

    // epilogue2: residual store
    #pragma unroll
    for (int mt = 0; mt < 2; ++mt)
        #pragma unroll
        for (int nt = 0; nt < 4; ++nt) {
            int cc = wc * 32 + nt * 8 + 2 * (lane & 3);
            int r0 = wr * 32 + mt * 16 + (lane >> 2);
            int r1 = r0 + 8;
            float* d = ac2[mt][nt];
            float v0 = fmaxf(d[0] + b1s[cc], 0.f), v1 = fmaxf(d[1] + b1s[cc + 1], 0.f);
            float v2 = fmaxf(d[2] + b1s[cc], 0.f), v3 = fmaxf(d[3] + b1s[cc + 1], 0.f);
            int n0 = tile0 + r0, n1 = tile0 + r1;
            if (n0 < NN) {
                float2 f = *reinterpret_cast<const float2*>(feat + (size_t)n0 * DD + cc);
                *reinterpret_cast<float2*>(outp + (size_t)n0 * DD + cc) =
                    make_float2(f.x + v0, f.y + v1);
            }
            if (n1 < NN) {
                float2 f = *reinterpret_cast<const float2*>(feat + (size_t)n1 * DD + cc);
                *reinterpret_cast<float2*>(outp + (size_t)n1 * DD + cc) =
                    make_float2(f.x + v2, f.y + v3);
            }
        }
}

// ============================== host launch =================================
extern "C" void kernel_launch(void* const* d_in, const int* in_sizes, int n_in,
                              void* d_out, int out_size)
{
    const float* feat  = (const float*)d_in[0];
    const int*   f_idx = (const int*)  d_in[1];
    const int*   t_idx = (const int*)  d_in[2];
    const float* msgW0 = (const float*)d_in[3];
    const float* msgb0 = (const float*)d_in[4];
    const float* msgW1 = (const float*)d_in[5];
    const float* msgb1 = (const float*)d_in[6];
    const float* updW0 = (const float*)d_in[7];
    const float* updb0 = (const float*)d_in[8];
    const float* updW1 = (const float*)d_in[9];
    const float* updb1 = (const float*)d_in[10];
    float* out = (float*)d_out;

    cudaFuncSetAttribute(pq_kernel,   cudaFuncAttributeMaxDynamicSharedMemorySize, P_SMEM);
    cudaFuncSetAttribute(edge_kernel, cudaFuncAttributeMaxDynamicSharedMemorySize, E_SMEM);
    cudaFuncSetAttribute(node_kernel, cudaFuncAttributeMaxDynamicSharedMemorySize, N_SMEM);

    conv_w_kernel<<<768, 256>>>(msgW0, updW0, msgW1, updW1);
    zero_agg_kernel<<<1024, 256>>>();

    const int pq_tiles   = (NN + TM - 1) / TM;  // 391
    const int node_tiles = (NN + TM - 1) / TM;  // 391

    pq_kernel<<<pq_tiles, 512, P_SMEM>>>(feat, msgb0, updb0);
    edge_kernel<<<152, 512, E_SMEM>>>(f_idx, t_idx, msgb1);
    node_kernel<<<node_tiles, 512, N_SMEM>>>(feat, updb1, out);
}

// round 16
// speedup vs baseline: 1.5936x; 1.1976x over previous
#include <cuda_runtime.h>
#include <cuda_bf16.h>
#include <cuda_fp16.h>
#include <cstdint>
#include <cstddef>

#define NN 50000
#define NE 600000
#define DD 128
#define HH 256
#define TM 128

// ============================ device scratch ================================
__device__ float g_agg[(size_t)NN * DD];
__device__ float g_PQ[(size_t)NN * 512];   // per-node [P|Q] for msg MLP
__device__ float g_R[(size_t)NN * HH];     // per-node R = feat@uW0b + updb0
// weights transposed to [N][K] row-major, single fp16
__device__ __half g_c0f[512 * DD];   // msg [W0a|W0b]^T : [512][128]
__device__ __half g_uaf[HH * DD];    // upd W0a^T: [256][128]
__device__ __half g_ubf[HH * DD];    // upd W0b^T: [256][128]
__device__ __half g_mW1f[DD * HH];   // msg W1^T: [128][256]
__device__ __half g_uW1f[DD * HH];   // upd W1^T: [128][256]

// ============================ PTX helpers ===================================
__device__ __forceinline__ uint32_t smem_u32(const void* p) {
    uint32_t a;
    asm("{ .reg .u64 t; cvta.to.shared.u64 t, %1; cvt.u32.u64 %0, t; }" : "=r"(a) : "l"(p));
    return a;
}
__device__ __forceinline__ void ldsm_x4(uint32_t& r0, uint32_t& r1, uint32_t& r2,
                                        uint32_t& r3, uint32_t addr) {
    asm volatile("ldmatrix.sync.aligned.m8n8.x4.shared.b16 {%0,%1,%2,%3}, [%4];"
                 : "=r"(r0), "=r"(r1), "=r"(r2), "=r"(r3) : "r"(addr));
}
__device__ __forceinline__ void mma_f16(float* d, const uint32_t* a,
                                        uint32_t b0, uint32_t b1) {
    asm volatile(
        "mma.sync.aligned.m16n8k16.row.col.f32.f16.f16.f32 "
        "{%0,%1,%2,%3},{%4,%5,%6,%7},{%8,%9},{%0,%1,%2,%3};"
        : "+f"(d[0]), "+f"(d[1]), "+f"(d[2]), "+f"(d[3])
        : "r"(a[0]), "r"(a[1]), "r"(a[2]), "r"(a[3]), "r"(b0), "r"(b1));
}
__device__ __forceinline__ uint32_t pack_f16(float a, float b) {
    __half2 t = __floats2half2_rn(a, b);
    return *reinterpret_cast<uint32_t*>(&t);
}
__device__ __forceinline__ void cpa16(uint32_t dst, const void* src) {
    asm volatile("cp.async.cg.shared.global [%0], [%1], 16;"
                 :: "r"(dst), "l"(src) : "memory");
}
#define CP_COMMIT() asm volatile("cp.async.commit_group;" ::: "memory")
#define CP_WAIT(n)  asm volatile("cp.async.wait_group %0;" :: "n"(n) : "memory")
__device__ __forceinline__ void red_add2(float* a, float v0, float v1) {
    asm volatile("red.global.add.v2.f32 [%0], {%1, %2};"
                 :: "l"(a), "f"(v0), "f"(v1) : "memory");
}
__device__ __forceinline__ void bar_q(int id) {
    asm volatile("bar.sync %0, 128;" :: "r"(id) : "memory");
}

// store float4 -> fp16 hi/lo pairs at byte offset off in two tiles
__device__ __forceinline__ void split_store_h(char* smc, int hi_base, int lo_base,
                                              int off, float4 v) {
    __half h0 = __float2half_rn(v.x), h1 = __float2half_rn(v.y);
    __half h2 = __float2half_rn(v.z), h3 = __float2half_rn(v.w);
    uint2 H, L;
    H.x = pack_f16(v.x, v.y);
    H.y = pack_f16(v.z, v.w);
    L.x = pack_f16(v.x - __half2float(h0), v.y - __half2float(h1));
    L.y = pack_f16(v.z - __half2float(h2), v.w - __half2float(h3));
    *reinterpret_cast<uint2*>(smc + hi_base + off) = H;
    *reinterpret_cast<uint2*>(smc + lo_base + off) = L;
}

// store float4 -> single fp16 at byte offset off
__device__ __forceinline__ void store_h4(char* smc, int base, int off, float4 v) {
    uint2 H;
    H.x = pack_f16(v.x, v.y);
    H.y = pack_f16(v.z, v.w);
    *reinterpret_cast<uint2*>(smc + base + off) = H;
}

__device__ __forceinline__ float4 relu_add4(float4 p, float4 q) {
    float4 v;
    v.x = fmaxf(p.x + q.x, 0.f);
    v.y = fmaxf(p.y + q.y, 0.f);
    v.z = fmaxf(p.z + q.z, 0.f);
    v.w = fmaxf(p.w + q.w, 0.f);
    return v;
}

// =========================== prelude kernels ================================
__global__ void zero_agg_kernel() {
    const size_t n4 = (size_t)NN * DD / 4;
    float4 z = make_float4(0.f, 0.f, 0.f, 0.f);
    for (size_t i = (size_t)blockIdx.x * blockDim.x + threadIdx.x; i < n4;
         i += (size_t)gridDim.x * blockDim.x)
        reinterpret_cast<float4*>(g_agg)[i] = z;
}

__global__ void conv_w_kernel(const float* __restrict__ mW0, const float* __restrict__ uW0,
                              const float* __restrict__ mW1, const float* __restrict__ uW1) {
    int i = blockIdx.x * blockDim.x + threadIdx.x;
    if (i >= 196608) return;
    if (i < 65536) {                      // msg [W0a|W0b]^T
        int n = i >> 7, k = i & 127;
        float w = (n < 256) ? mW0[k * HH + n] : mW0[(128 + k) * HH + (n - 256)];
        g_c0f[n * DD + k] = __float2half_rn(w);
    } else if (i < 98304) {               // upd W0a^T (agg part)
        int j = i - 65536, n = j >> 7, k = j & 127;
        g_uaf[n * DD + k] = __float2half_rn(uW0[k * HH + n]);
    } else if (i < 131072) {              // upd W0b^T (feat part)
        int j = i - 98304, n = j >> 7, k = j & 127;
        g_ubf[n * DD + k] = __float2half_rn(uW0[(DD + k) * HH + n]);
    } else if (i < 163840) {              // msg W1^T
        int j = i - 131072, k = j >> 7, n = j & 127;
        g_mW1f[n * HH + k] = __float2half_rn(mW1[j]);
    } else {                              // upd W1^T
        int j = i - 163840, k = j >> 7, n = j & 127;
        g_uW1f[n * HH + k] = __float2half_rn(uW1[j]);
    }
}

// single-fp16 B-chunk stager: nrows x 32 K-cols, BROW=80, 512 threads
__device__ __forceinline__ void stage_bf(uint32_t bbase, int tid,
                                         const __half* Wf,
                                         int row_base, int chunk, int nrows,
                                         int kstride) {
    #pragma unroll
    for (int i = 0; i < 2; ++i) {
        int idx = tid + i * 512;
        if (idx < nrows * 4) {
            int row = idx >> 2, seg = idx & 3;
            uint32_t d = bbase + (uint32_t)(row * 80 + seg * 16);
            cpa16(d, Wf + (row_base + row) * kstride + chunk * 32 + seg * 8);
        }
    }
}

// ======================= PQ+R precompute kernel =============================
// h=0: P = feat@msgW0a + msgb0 ; h=1: Q = feat@msgW0b ; h=2: R = feat@updW0b + updb0
// A: feat fp16 hi/lo; B: single fp16 -> 2-pass mma_f16
#define P_B0    0
#define P_UB0   1024
#define P_AHI   4096
#define P_ALO   (4096 + 34816)          // 38912
#define P_B     (38912 + 34816)         // 73728
#define P_BBUF  20480
#define P_SMEM  (73728 + 2 * P_BBUF)    // 114688
#define AROW2   272

__global__ void __launch_bounds__(512, 1) pq_kernel(const float* __restrict__ feat,
                                                    const float* __restrict__ b0,
                                                    const float* __restrict__ ub0) {
    extern __shared__ char smc[];
    const uint32_t sb = smem_u32(smc);
    const int tid  = threadIdx.x;
    const int wid  = tid >> 5;
    const int lane = tid & 31;
    const int wr   = wid & 3;
    const int wc   = wid >> 2;
    const int lrow = ((lane >> 3) & 1) * 8 + (lane & 7);
    const int lcol = (lane >> 4) * 8;
    float* b0s  = reinterpret_cast<float*>(smc + P_B0);
    float* ub0s = reinterpret_cast<float*>(smc + P_UB0);

    const int tile0 = blockIdx.x * TM;
    if (tid < 256) b0s[tid] = b0[tid];
    else ub0s[tid - 256] = ub0[tid - 256];

    stage_bf(sb + P_B, tid, g_c0f, 0, 0, 256, DD);
    CP_COMMIT();

    {
        const float4* f4 = reinterpret_cast<const float4*>(feat);
        #pragma unroll
        for (int it = 0; it < 8; ++it) {
            int ci = tid + it * 512;
            int r  = ci >> 5;
            int c4 = ci & 31;
            int node = tile0 + r;
            float4 v = make_float4(0.f, 0.f, 0.f, 0.f);
            if (node < NN) v = f4[(size_t)node * 32 + c4];
            split_store_h(smc, P_AHI, P_ALO, r * AROW2 + c4 * 8, v);
        }
    }
    __syncthreads();

    for (int h = 0; h < 3; ++h) {
        float acc[2][8][4];
        #pragma unroll
        for (int m = 0; m < 2; ++m)
            #pragma unroll
            for (int n = 0; n < 8; ++n)
                #pragma unroll
                for (int q = 0; q < 4; ++q) acc[m][n][q] = 0.f;

        for (int c = 0; c < 4; ++c) {
            int gg = h * 4 + c;
            if (gg < 11) {
                int gn = gg + 1, hn = gn >> 2, cn = gn & 3;
                const __half* Wf = (hn < 2) ? g_c0f : g_ubf;
                int rb = (hn == 1) ? 256 : 0;
                stage_bf(sb + P_B + (uint32_t)(gn & 1) * P_BBUF, tid,
                         Wf, rb, cn, 256, DD);
            }
            CP_COMMIT();
            CP_WAIT(1);
            __syncthreads();
            const uint32_t bbase = sb + P_B + (uint32_t)(gg & 1) * P_BBUF;
            #pragma unroll
            for (int ks = 0; ks < 2; ++ks) {
                const int kA = c * 32 + ks * 16;
                uint32_t ah[2][4], al[2][4];
                #pragma unroll
                for (int mt = 0; mt < 2; ++mt) {
                    uint32_t aaddr = sb + P_AHI +
                        (uint32_t)((wr * 32 + mt * 16 + lrow) * AROW2 + (kA + lcol) * 2);
                    ldsm_x4(ah[mt][0], ah[mt][1], ah[mt][2], ah[mt][3], aaddr);
                    ldsm_x4(al[mt][0], al[mt][1], al[mt][2], al[mt][3],
                            aaddr + (P_ALO - P_AHI));
                }
                #pragma unroll
                for (int np = 0; np < 4; ++np) {
                    uint32_t baddr = bbase +
                        (uint32_t)((wc * 64 + np * 16 + lrow) * 80 + (ks * 16 + lcol) * 2);
                    uint32_t bh0, bh1, bh2, bh3;
                    ldsm_x4(bh0, bh1, bh2, bh3, baddr);
                    const int nb = np * 2;
                    #pragma unroll
                    for (int mt = 0; mt < 2; ++mt) {
                        mma_f16(acc[mt][nb],     ah[mt], bh0, bh2);
                        mma_f16(acc[mt][nb + 1], ah[mt], bh1, bh3);
                        mma_f16(acc[mt][nb],     al[mt], bh0, bh2);
                        mma_f16(acc[mt][nb + 1], al[mt], bh1, bh3);
                    }
                }
            }
            __syncthreads();
        }

        #pragma unroll
        for (int mt = 0; mt < 2; ++mt)
            #pragma unroll
            for (int nt = 0; nt < 8; ++nt) {
                int cc = wc * 64 + nt * 8 + 2 * (lane & 3);
                int r0 = wr * 32 + mt * 16 + (lane >> 2);
                int r1 = r0 + 8;
                float* d = acc[mt][nt];
                float bb0 = (h == 0) ? b0s[cc]      : (h == 2) ? ub0s[cc]     : 0.f;
                float bb1 = (h == 0) ? b0s[cc + 1]  : (h == 2) ? ub0s[cc + 1] : 0.f;
                int n0 = tile0 + r0, n1 = tile0 + r1;
                if (h < 2) {
                    int co = h * 256 + cc;
                    if (n0 < NN)
                        *reinterpret_cast<float2*>(g_PQ + (size_t)n0 * 512 + co) =
                            make_float2(d[0] + bb0, d[1] + bb1);
                    if (n1 < NN)
                        *reinterpret_cast<float2*>(g_PQ + (size_t)n1 * 512 + co) =
                            make_float2(d[2] + bb0, d[3] + bb1);
                } else {
                    if (n0 < NN)
                        *reinterpret_cast<float2*>(g_R + (size_t)n0 * HH + cc) =
                            make_float2(d[0] + bb0, d[1] + bb1);
                    if (n1 < NN)
                        *reinterpret_cast<float2*>(g_R + (size_t)n1 * HH + cc) =
                            make_float2(d[2] + bb0, d[3] + bb1);
                }
            }
    }
}

// ============== edge kernel (persistent, FOUR independent groups) ===========
// 1-pass pure fp16: H single fp16 (A), W1 single fp16 (B) -> 8 MMA, 4 LDSM
// per K16 per warp. W1 resident = 80 KB; A bufs single (2560B each).
#define TME    32                      // edge rows per group-tile
#define E_B1   0                       // 128 floats
#define E_TO   512                     // 8 x 32 ints: [g][parity]
#define E_A    4096                    // per group: 2 bufs x 2560B (single fp16)
#define E_B    (4096 + 20480)          // 24576; B: 8 chunks * 10240 (fp16)
#define E_SMEM (24576 + 81920)         // 106496

#define EDGE_T32 (NE / TME)            // 18750

__global__ void __launch_bounds__(512, 1) edge_kernel(
    const int* __restrict__ from_idx, const int* __restrict__ to_idx,
    const float* __restrict__ b1)
{
    extern __shared__ char smc[];
    const uint32_t sb = smem_u32(smc);
    const int tid  = threadIdx.x;
    const int wid  = tid >> 5;
    const int lane = tid & 31;
    const int g    = wid >> 2;            // group 0..3
    const int wc   = wid & 3;             // col group 0..3 (32 cols each)
    const int lrow = ((lane >> 3) & 1) * 8 + (lane & 7);
    const int lcol = (lane >> 4) * 8;
    const int barid = 1 + g;

    float* b1s = reinterpret_cast<float*>(smc + E_B1);
    if (tid < 128) b1s[tid] = b1[tid];

    // ---- stage resident W1 (fp16) once ----
    #pragma unroll
    for (int i = 0; i < 8; ++i) {
        int idx = tid + i * 512;          // c*512 + row*4 + seg
        int c = idx >> 9, rs = idx & 511;
        int row = rs >> 2, seg = rs & 3;
        uint32_t d = sb + E_B + (uint32_t)(c * 10240 + row * 80 + seg * 16);
        cpa16(d, g_mW1f + row * HH + c * 32 + seg * 8);
    }
    CP_COMMIT();
    CP_WAIT(0);
    __syncthreads();                      // last full-CTA sync

    // hoist bias values into registers (constant across tiles)
    float bv0[4], bv1[4];
    #pragma unroll
    for (int nt = 0; nt < 4; ++nt) {
        int cc = wc * 32 + nt * 8 + 2 * (lane & 3);
        bv0[nt] = b1s[cc];
        bv1[nt] = b1s[cc + 1];
    }

    const float4* pq4 = reinterpret_cast<const float4*>(g_PQ);
    const int ptid = tid & 127;           // group-local thread id
    const int r  = ptid >> 2;             // local row 0..31
    const int sg = ptid & 3;              // seg: 2 float4 per seg
    const int ga = E_A + g * 5120;        // group A buffers (2 x 2560B)

    int tile = blockIdx.x * 4 + g;
    int fr = 0, to = 0;
    if (tile < EDGE_T32) {
        fr = from_idx[tile * TME + r];
        to = to_idx[tile * TME + r];
    }

    int tcnt = 0;
    for (; tile < EDGE_T32; tile += gridDim.x * 4, ++tcnt) {
        int* stob = reinterpret_cast<int*>(smc + E_TO + (g * 2 + (tcnt & 1)) * 128);
        if (sg == 0) stob[r] = to;

        const size_t prow = (size_t)fr * 128 + sg * 2;        // float4 units
        const size_t qrow = (size_t)to * 128 + 64 + sg * 2;

        // produce chunk 0 into buf 0
        {
            float4 p0 = pq4[prow], p1 = pq4[prow + 1];
            float4 q0 = pq4[qrow], q1 = pq4[qrow + 1];
            int off = r * 80 + sg * 16;
            store_h4(smc, ga, off,     relu_add4(p0, q0));
            store_h4(smc, ga, off + 8, relu_add4(p1, q1));
        }
        bar_q(barid);

        // prefetch next tile's indices (latency hidden under 8 MMA chunks)
        int frN = 0, toN = 0;
        {
            int tnext = tile + gridDim.x * 4;
            if (tnext < EDGE_T32) {
                frN = from_idx[tnext * TME + r];
                toN = to_idx[tnext * TME + r];
            }
        }

        float ac2[2][4][4];
        #pragma unroll
        for (int m = 0; m < 2; ++m)
            #pragma unroll
            for (int n = 0; n < 4; ++n)
                #pragma unroll
                for (int q = 0; q < 4; ++q) ac2[m][n][q] = 0.f;

        #pragma unroll
        for (int c = 0; c < 8; ++c) {
            // issue next chunk's gathers (latency hidden by MMA below)
            float4 p0, p1, q0, q1;
            if (c < 7) {
                p0 = pq4[prow + (c + 1) * 8];
                p1 = pq4[prow + (c + 1) * 8 + 1];
                q0 = pq4[qrow + (c + 1) * 8];
                q1 = pq4[qrow + (c + 1) * 8 + 1];
            }
            const uint32_t abase = sb + (uint32_t)(ga + (c & 1) * 2560);
            const uint32_t bbase = sb + E_B + (uint32_t)(c * 10240);
            #pragma unroll
            for (int ks = 0; ks < 2; ++ks) {
                uint32_t ah[2][4];
                #pragma unroll
                for (int mt = 0; mt < 2; ++mt) {
                    uint32_t aaddr = abase +
                        (uint32_t)((mt * 16 + lrow) * 80 + (ks * 16 + lcol) * 2);
                    ldsm_x4(ah[mt][0], ah[mt][1], ah[mt][2], ah[mt][3], aaddr);
                }
                #pragma unroll
                for (int np = 0; np < 2; ++np) {
                    uint32_t baddr = bbase +
                        (uint32_t)((wc * 32 + np * 16 + lrow) * 80 + (ks * 16 + lcol) * 2);
                    uint32_t bh0, bh1, bh2, bh3;
                    ldsm_x4(bh0, bh1, bh2, bh3, baddr);
                    const int nb = np * 2;
                    #pragma unroll
                    for (int mt = 0; mt < 2; ++mt) {
                        mma_f16(ac2[mt][nb],     ah[mt], bh0, bh2);
                        mma_f16(ac2[mt][nb + 1], ah[mt], bh1, bh3);
                    }
                }
            }
            if (c < 7) {
                const int ab = ga + ((c + 1) & 1) * 2560;
                int off = r * 80 + sg * 16;
                store_h4(smc, ab, off,     relu_add4(p0, q0));
                store_h4(smc, ab, off + 8, relu_add4(p1, q1));
            }
            bar_q(barid);
        }

        // ---- epilogue: bias+relu, vectorized red scatter ----
        const int* stor =
            reinterpret_cast<const int*>(smc + E_TO + (g * 2 + (tcnt & 1)) * 128);
        #pragma unroll
        for (int mt = 0; mt < 2; ++mt)
            #pragma unroll
            for (int nt = 0; nt < 4; ++nt) {
                int cc = wc * 32 + nt * 8 + 2 * (lane & 3);
                int r0 = mt * 16 + (lane >> 2);
                int r1 = r0 + 8;
                float* d = ac2[mt][nt];
                float v0 = fmaxf(d[0] + bv0[nt], 0.f), v1 = fmaxf(d[1] + bv1[nt], 0.f);
                float v2 = fmaxf(d[2] + bv0[nt], 0.f), v3 = fmaxf(d[3] + bv1[nt], 0.f);
                red_add2(g_agg + (size_t)stor[r0] * DD + cc, v0, v1);
                red_add2(g_agg + (size_t)stor[r1] * DD + cc, v2, v3);
            }

        fr = frN;
        to = toN;
    }
}

// ============================ node kernel (K-folded) ========================
// S = agg@uW0a (K=128); h = relu(S + R[n]); out = feat + relu(h@uW1 + b1)
// A: fp16 hi/lo, B: single fp16 -> 2-pass mma_f16
#define SM_B1   1024
#define SM_AHI  4096
#define SM_ALO  (4096 + 67584)          // 71680
#define SM_B    (71680 + 67584)         // 139264
#define N_BBUF  20480
#define N_SMEM  (139264 + 2 * N_BBUF)   // 180224
#define AROW 528

__global__ void __launch_bounds__(512, 1) node_kernel(
    const float* __restrict__ feat,
    const float* __restrict__ b1,
    float* __restrict__ outp)
{
    extern __shared__ char smc[];
    const uint32_t sb = smem_u32(smc);
    const int tid  = threadIdx.x;
    const int wid  = tid >> 5;
    const int lane = tid & 31;
    const int wr   = wid & 3;
    const int wc   = wid >> 2;
    const int lrow = ((lane >> 3) & 1) * 8 + (lane & 7);
    const int lcol = (lane >> 4) * 8;

    float* b1s = reinterpret_cast<float*>(smc + SM_B1);

    const int tile0 = blockIdx.x * TM;

    if (tid < 128) b1s[tid] = b1[tid];

    stage_bf(sb + SM_B, tid, g_uaf, 0, 0, 256, DD);
    CP_COMMIT();
    __syncthreads();

    // gather agg tile [128 x 128]
    {
        const float4* a4 = reinterpret_cast<const float4*>(g_agg);
        #pragma unroll
        for (int it = 0; it < 8; ++it) {
            int ci = tid + it * 512;
            int r  = ci >> 5;
            int c4 = ci & 31;
            int node = tile0 + r;
            float4 v = make_float4(0.f, 0.f, 0.f, 0.f);
            if (node < NN) v = a4[(size_t)node * 32 + c4];
            split_store_h(smc, SM_AHI, SM_ALO, r * AROW + c4 * 8, v);
        }
    }
    __syncthreads();

    // GEMM1: S = agg@uW0a, K=128 -> 4 chunks
    float acc[2][8][4];
    #pragma unroll
    for (int m = 0; m < 2; ++m)
        #pragma unroll
        for (int n = 0; n < 8; ++n)
            #pragma unroll
            for (int q = 0; q < 4; ++q) acc[m][n][q] = 0.f;

    for (int c = 0; c < 4; ++c) {
        if (c < 3)
            stage_bf(sb + SM_B + (uint32_t)((c + 1) & 1) * N_BBUF, tid,
                     g_uaf, 0, c + 1, 256, DD);
        CP_COMMIT();
        CP_WAIT(1);
        __syncthreads();
        const uint32_t bbase = sb + SM_B + (uint32_t)(c & 1) * N_BBUF;
        #pragma unroll
        for (int ks = 0; ks < 2; ++ks) {
            const int kA = c * 32 + ks * 16;
            uint32_t ah[2][4], al[2][4];
            #pragma unroll
            for (int mt = 0; mt < 2; ++mt) {
                uint32_t aaddr = sb + SM_AHI +
                    (uint32_t)((wr * 32 + mt * 16 + lrow) * AROW + (kA + lcol) * 2);
                ldsm_x4(ah[mt][0], ah[mt][1], ah[mt][2], ah[mt][3], aaddr);
                ldsm_x4(al[mt][0], al[mt][1], al[mt][2], al[mt][3],
                        aaddr + (SM_ALO - SM_AHI));
            }
            #pragma unroll
            for (int np = 0; np < 4; ++np) {
                uint32_t baddr = bbase +
                    (uint32_t)((wc * 64 + np * 16 + lrow) * 80 + (ks * 16 + lcol) * 2);
                uint32_t bh0, bh1, bh2, bh3;
                ldsm_x4(bh0, bh1, bh2, bh3, baddr);
                const int nb = np * 2;
                #pragma unroll
                for (int mt = 0; mt < 2; ++mt) {
                    mma_f16(acc[mt][nb],     ah[mt], bh0, bh2);
                    mma_f16(acc[mt][nb + 1], ah[mt], bh1, bh3);
                    mma_f16(acc[mt][nb],     al[mt], bh0, bh2);
                    mma_f16(acc[mt][nb + 1], al[mt], bh1, bh3);
                }
            }
        }
        __syncthreads();
    }

    stage_bf(sb + SM_B, tid, g_uW1f, 0, 0, 128, HH);
    CP_COMMIT();

    // epilogue1: h = relu(S + R[n]) back into A tiles (fp16 hi/lo)
    #pragma unroll
    for (int mt = 0; mt < 2; ++mt)
        #pragma unroll
        for (int nt = 0; nt < 8; ++nt) {
            int cc = wc * 64 + nt * 8 + 2 * (lane & 3);
            int r0 = wr * 32 + mt * 16 + (lane >> 2);
            int n0 = tile0 + r0, n1 = n0 + 8;
            float* d = acc[mt][nt];
            float2 R0 = make_float2(0.f, 0.f), R1 = make_float2(0.f, 0.f);
            if (n0 < NN) R0 = *reinterpret_cast<const float2*>(g_R + (size_t)n0 * HH + cc);
            if (n1 < NN) R1 = *reinterpret_cast<const float2*>(g_R + (size_t)n1 * HH + cc);
            float v0 = fmaxf(d[0] + R0.x, 0.f), v1 = fmaxf(d[1] + R0.y, 0.f);
            float v2 = fmaxf(d[2] + R1.x, 0.f), v3 = fmaxf(d[3] + R1.y, 0.f);
            __half h0 = __float2half_rn(v0), h1 = __float2half_rn(v1);
            __half h2 = __float2half_rn(v2), h3 = __float2half_rn(v3);
            int o0 = r0 * AROW + cc * 2;
            int o1 = (r0 + 8) * AROW + cc * 2;
            *reinterpret_cast<uint32_t*>(smc + SM_AHI + o0) = pack_f16(v0, v1);
            *reinterpret_cast<uint32_t*>(smc + SM_AHI + o1) = pack_f16(v2, v3);
            *reinterpret_cast<uint32_t*>(smc + SM_ALO + o0) =
                pack_f16(v0 - __half2float(h0), v1 - __half2float(h1));
            *reinterpret_cast<uint32_t*>(smc + SM_ALO + o1) =
                pack_f16(v2 - __half2float(h2), v3 - __half2float(h3));
        }

    // GEMM2: M = h@uW1, K=256 -> 8 chunks
    float ac2[2][4][4];
    #pragma unroll
    for (int m = 0; m < 2; ++m)
        #pragma unroll
        for (int n = 0; n < 4; ++n)
            #pragma unroll
            for (int q = 0; q < 4; ++q) ac2[m][n][q] = 0.f;

    for (int c = 0; c < 8; ++c) {
        if (c < 7)
            stage_bf(sb + SM_B + (uint32_t)((c + 1) & 1) * N_BBUF, tid,
                     g_uW1f, 0, c + 1, 128, HH);
        CP_COMMIT();
        CP_WAIT(1);
        __syncthreads();
        const uint32_t bbase = sb + SM_B + (uint32_t)(c & 1) * N_BBUF;
        #pragma unroll
        for (int ks = 0; ks < 2; ++ks) {
            const int kA = c * 32 + ks * 16;
            uint32_t ah[2][4], al[2][4];
            #pragma unroll
            for (int mt = 0; mt < 2; ++mt) {
                uint32_t aaddr = sb + SM_AHI +
                    (uint32_t)((wr * 32 + mt * 16 + lrow) * AROW + (kA + lcol) * 2);
                ldsm_x4(ah[mt][0], ah[mt][1], ah[mt][2], ah[mt][3], aaddr);
                ldsm_x4(al[mt][0], al[mt][1], al[mt][2], al[mt][3],
                        aaddr + (SM_ALO - SM_AHI));
            }
            #pragma unroll
            for (int np = 0; np < 2; ++np) {
                uint32_t baddr = bbase +
                    (uint32_t)((wc * 32 + np * 16 + lrow) * 80 + (ks * 16 + lcol) * 2);
                uint32_t bh0, bh1, bh2, bh3;
                ldsm_x4(bh0, bh1, bh2, bh3, baddr);
                const int nb = np * 2;
                #pragma unroll
                for (int mt = 0; mt < 2; ++mt) {
                    mma_f16(ac2[mt][nb],     ah[mt], bh0, bh2);
                    mma_f16(ac2[mt][nb + 1], ah[mt], bh1, bh3);
                    mma_f16(ac2[mt][nb],     al[mt], bh0, bh2);
                    mma_f16(ac2[mt][nb + 1], al[mt], bh1, bh3);
                }
            }
        }
        __syncthreads();
    }

    // epilogue2: residual store
    #pragma unroll
    for (int mt = 0; mt < 2; ++mt)
        #pragma unroll
        for (int nt = 0; nt < 4; ++nt) {
            int cc = wc * 32 + nt * 8 + 2 * (lane & 3);
            int r0 = wr * 32 + mt * 16 + (lane >> 2);
            int r1 = r0 + 8;
            float* d = ac2[mt][nt];
            float v0 = fmaxf(d[0] + b1s[cc], 0.f), v1 = fmaxf(d[1] + b1s[cc + 1], 0.f);
            float v2 = fmaxf(d[2] + b1s[cc], 0.f), v3 = fmaxf(d[3] + b1s[cc + 1], 0.f);
            int n0 = tile0 + r0, n1 = tile0 + r1;
            if (n0 < NN) {
                float2 f = *reinterpret_cast<const float2*>(feat + (size_t)n0 * DD + cc);
                *reinterpret_cast<float2*>(outp + (size_t)n0 * DD + cc) =
                    make_float2(f.x + v0, f.y + v1);
            }
            if (n1 < NN) {
                float2 f = *reinterpret_cast<const float2*>(feat + (size_t)n1 * DD + cc);
                *reinterpret_cast<float2*>(outp + (size_t)n1 * DD + cc) =
                    make_float2(f.x + v2, f.y + v3);
            }
        }
}

// ============================== host launch =================================
extern "C" void kernel_launch(void* const* d_in, const int* in_sizes, int n_in,
                              void* d_out, int out_size)
{
    const float* feat  = (const float*)d_in[0];
    const int*   f_idx = (const int*)  d_in[1];
    const int*   t_idx = (const int*)  d_in[2];
    const float* msgW0 = (const float*)d_in[3];
    const float* msgb0 = (const float*)d_in[4];
    const float* msgW1 = (const float*)d_in[5];
    const float* msgb1 = (const float*)d_in[6];
    const float* updW0 = (const float*)d_in[7];
    const float* updb0 = (const float*)d_in[8];
    const float* updW1 = (const float*)d_in[9];
    const float* updb1 = (const float*)d_in[10];
    float* out = (float*)d_out;

    cudaFuncSetAttribute(pq_kernel,   cudaFuncAttributeMaxDynamicSharedMemorySize, P_SMEM);
    cudaFuncSetAttribute(edge_kernel, cudaFuncAttributeMaxDynamicSharedMemorySize, E_SMEM);
    cudaFuncSetAttribute(node_kernel, cudaFuncAttributeMaxDynamicSharedMemorySize, N_SMEM);

    conv_w_kernel<<<768, 256>>>(msgW0, updW0, msgW1, updW1);
    zero_agg_kernel<<<1024, 256>>>();

    const int pq_tiles   = (NN + TM - 1) / TM;  // 391
    const int node_tiles = (NN + TM - 1) / TM;  // 391

    pq_kernel<<<pq_tiles, 512, P_SMEM>>>(feat, msgb0, updb0);
    edge_kernel<<<152, 512, E_SMEM>>>(f_idx, t_idx, msgb1);
    node_kernel<<<node_tiles, 512, N_SMEM>>>(feat, updb1, out);
}

// round 17
// speedup vs baseline: 2.0309x; 1.2744x over previous
#include <cuda_runtime.h>
#include <cuda_bf16.h>
#include <cuda_fp16.h>
#include <cstdint>
#include <cstddef>

#define NN 50000
#define NE 600000
#define DD 128
#define HH 256
#define TM 128

// ============================ device scratch ================================
__device__ float  g_agg[(size_t)NN * DD];
__device__ __half g_PQh[(size_t)NN * 512];  // per-node [P|Q] (fp16) for msg MLP
__device__ float  g_R[(size_t)NN * HH];     // per-node R = feat@uW0b + updb0
// weights transposed to [N][K] row-major, single fp16
__device__ __half g_c0f[512 * DD];   // msg [W0a|W0b]^T : [512][128]
__device__ __half g_uaf[HH * DD];    // upd W0a^T: [256][128]
__device__ __half g_ubf[HH * DD];    // upd W0b^T: [256][128]
__device__ __half g_mW1f[DD * HH];   // msg W1^T: [128][256]
__device__ __half g_uW1f[DD * HH];   // upd W1^T: [128][256]

// ============================ PTX helpers ===================================
__device__ __forceinline__ uint32_t smem_u32(const void* p) {
    uint32_t a;
    asm("{ .reg .u64 t; cvta.to.shared.u64 t, %1; cvt.u32.u64 %0, t; }" : "=r"(a) : "l"(p));
    return a;
}
__device__ __forceinline__ void ldsm_x4(uint32_t& r0, uint32_t& r1, uint32_t& r2,
                                        uint32_t& r3, uint32_t addr) {
    asm volatile("ldmatrix.sync.aligned.m8n8.x4.shared.b16 {%0,%1,%2,%3}, [%4];"
                 : "=r"(r0), "=r"(r1), "=r"(r2), "=r"(r3) : "r"(addr));
}
__device__ __forceinline__ void mma_f16(float* d, const uint32_t* a,
                                        uint32_t b0, uint32_t b1) {
    asm volatile(
        "mma.sync.aligned.m16n8k16.row.col.f32.f16.f16.f32 "
        "{%0,%1,%2,%3},{%4,%5,%6,%7},{%8,%9},{%0,%1,%2,%3};"
        : "+f"(d[0]), "+f"(d[1]), "+f"(d[2]), "+f"(d[3])
        : "r"(a[0]), "r"(a[1]), "r"(a[2]), "r"(a[3]), "r"(b0), "r"(b1));
}
__device__ __forceinline__ uint32_t pack_f16(float a, float b) {
    __half2 t = __floats2half2_rn(a, b);
    return *reinterpret_cast<uint32_t*>(&t);
}
__device__ __forceinline__ void cpa16(uint32_t dst, const void* src) {
    asm volatile("cp.async.cg.shared.global [%0], [%1], 16;"
                 :: "r"(dst), "l"(src) : "memory");
}
#define CP_COMMIT() asm volatile("cp.async.commit_group;" ::: "memory")
#define CP_WAIT(n)  asm volatile("cp.async.wait_group %0;" :: "n"(n) : "memory")
__device__ __forceinline__ void red_add2(float* a, float v0, float v1) {
    asm volatile("red.global.add.v2.f32 [%0], {%1, %2};"
                 :: "l"(a), "f"(v0), "f"(v1) : "memory");
}
__device__ __forceinline__ void bar_q(int id) {
    asm volatile("bar.sync %0, 128;" :: "r"(id) : "memory");
}

// half2 add + relu on packed uint32
__device__ __forceinline__ uint32_t hadd_relu2(uint32_t a, uint32_t b) {
    __half2 x = *reinterpret_cast<__half2*>(&a);
    __half2 y = *reinterpret_cast<__half2*>(&b);
    __half2 z = __floats2half2_rn(0.f, 0.f);
    __half2 s = __hmax2(__hadd2(x, y), z);
    return *reinterpret_cast<uint32_t*>(&s);
}
// combine two uint4 of packed halves: relu(P+Q)
__device__ __forceinline__ uint4 relu_add_h8(uint4 P, uint4 Q) {
    uint4 o;
    o.x = hadd_relu2(P.x, Q.x);
    o.y = hadd_relu2(P.y, Q.y);
    o.z = hadd_relu2(P.z, Q.z);
    o.w = hadd_relu2(P.w, Q.w);
    return o;
}

// store float4 -> fp16 hi/lo pairs at byte offset off in two tiles
__device__ __forceinline__ void split_store_h(char* smc, int hi_base, int lo_base,
                                              int off, float4 v) {
    __half h0 = __float2half_rn(v.x), h1 = __float2half_rn(v.y);
    __half h2 = __float2half_rn(v.z), h3 = __float2half_rn(v.w);
    uint2 H, L;
    H.x = pack_f16(v.x, v.y);
    H.y = pack_f16(v.z, v.w);
    L.x = pack_f16(v.x - __half2float(h0), v.y - __half2float(h1));
    L.y = pack_f16(v.z - __half2float(h2), v.w - __half2float(h3));
    *reinterpret_cast<uint2*>(smc + hi_base + off) = H;
    *reinterpret_cast<uint2*>(smc + lo_base + off) = L;
}

// =========================== prelude kernels ================================
__global__ void zero_agg_kernel() {
    const size_t n4 = (size_t)NN * DD / 4;
    float4 z = make_float4(0.f, 0.f, 0.f, 0.f);
    for (size_t i = (size_t)blockIdx.x * blockDim.x + threadIdx.x; i < n4;
         i += (size_t)gridDim.x * blockDim.x)
        reinterpret_cast<float4*>(g_agg)[i] = z;
}

__global__ void conv_w_kernel(const float* __restrict__ mW0, const float* __restrict__ uW0,
                              const float* __restrict__ mW1, const float* __restrict__ uW1) {
    int i = blockIdx.x * blockDim.x + threadIdx.x;
    if (i >= 196608) return;
    if (i < 65536) {                      // msg [W0a|W0b]^T
        int n = i >> 7, k = i & 127;
        float w = (n < 256) ? mW0[k * HH + n] : mW0[(128 + k) * HH + (n - 256)];
        g_c0f[n * DD + k] = __float2half_rn(w);
    } else if (i < 98304) {               // upd W0a^T (agg part)
        int j = i - 65536, n = j >> 7, k = j & 127;
        g_uaf[n * DD + k] = __float2half_rn(uW0[k * HH + n]);
    } else if (i < 131072) {              // upd W0b^T (feat part)
        int j = i - 98304, n = j >> 7, k = j & 127;
        g_ubf[n * DD + k] = __float2half_rn(uW0[(DD + k) * HH + n]);
    } else if (i < 163840) {              // msg W1^T
        int j = i - 131072, k = j >> 7, n = j & 127;
        g_mW1f[n * HH + k] = __float2half_rn(mW1[j]);
    } else {                              // upd W1^T
        int j = i - 163840, k = j >> 7, n = j & 127;
        g_uW1f[n * HH + k] = __float2half_rn(uW1[j]);
    }
}

// single-fp16 B-chunk stager: nrows x 32 K-cols, BROW=80, 512 threads
__device__ __forceinline__ void stage_bf(uint32_t bbase, int tid,
                                         const __half* Wf,
                                         int row_base, int chunk, int nrows,
                                         int kstride) {
    #pragma unroll
    for (int i = 0; i < 2; ++i) {
        int idx = tid + i * 512;
        if (idx < nrows * 4) {
            int row = idx >> 2, seg = idx & 3;
            uint32_t d = bbase + (uint32_t)(row * 80 + seg * 16);
            cpa16(d, Wf + (row_base + row) * kstride + chunk * 32 + seg * 8);
        }
    }
}

// ======================= PQ+R precompute kernel =============================
// h=0: P = feat@msgW0a + msgb0 ; h=1: Q = feat@msgW0b ; h=2: R = feat@updW0b + updb0
// A: feat fp16 hi/lo; B: single fp16 -> 2-pass mma_f16. P,Q stored fp16.
#define P_B0    0
#define P_UB0   1024
#define P_AHI   4096
#define P_ALO   (4096 + 34816)          // 38912
#define P_B     (38912 + 34816)         // 73728
#define P_BBUF  20480
#define P_SMEM  (73728 + 2 * P_BBUF)    // 114688
#define AROW2   272

__global__ void __launch_bounds__(512, 1) pq_kernel(const float* __restrict__ feat,
                                                    const float* __restrict__ b0,
                                                    const float* __restrict__ ub0) {
    extern __shared__ char smc[];
    const uint32_t sb = smem_u32(smc);
    const int tid  = threadIdx.x;
    const int wid  = tid >> 5;
    const int lane = tid & 31;
    const int wr   = wid & 3;
    const int wc   = wid >> 2;
    const int lrow = ((lane >> 3) & 1) * 8 + (lane & 7);
    const int lcol = (lane >> 4) * 8;
    float* b0s  = reinterpret_cast<float*>(smc + P_B0);
    float* ub0s = reinterpret_cast<float*>(smc + P_UB0);

    const int tile0 = blockIdx.x * TM;
    if (tid < 256) b0s[tid] = b0[tid];
    else ub0s[tid - 256] = ub0[tid - 256];

    stage_bf(sb + P_B, tid, g_c0f, 0, 0, 256, DD);
    CP_COMMIT();

    {
        const float4* f4 = reinterpret_cast<const float4*>(feat);
        #pragma unroll
        for (int it = 0; it < 8; ++it) {
            int ci = tid + it * 512;
            int r  = ci >> 5;
            int c4 = ci & 31;
            int node = tile0 + r;
            float4 v = make_float4(0.f, 0.f, 0.f, 0.f);
            if (node < NN) v = f4[(size_t)node * 32 + c4];
            split_store_h(smc, P_AHI, P_ALO, r * AROW2 + c4 * 8, v);
        }
    }
    __syncthreads();

    for (int h = 0; h < 3; ++h) {
        float acc[2][8][4];
        #pragma unroll
        for (int m = 0; m < 2; ++m)
            #pragma unroll
            for (int n = 0; n < 8; ++n)
                #pragma unroll
                for (int q = 0; q < 4; ++q) acc[m][n][q] = 0.f;

        for (int c = 0; c < 4; ++c) {
            int gg = h * 4 + c;
            if (gg < 11) {
                int gn = gg + 1, hn = gn >> 2, cn = gn & 3;
                const __half* Wf = (hn < 2) ? g_c0f : g_ubf;
                int rb = (hn == 1) ? 256 : 0;
                stage_bf(sb + P_B + (uint32_t)(gn & 1) * P_BBUF, tid,
                         Wf, rb, cn, 256, DD);
            }
            CP_COMMIT();
            CP_WAIT(1);
            __syncthreads();
            const uint32_t bbase = sb + P_B + (uint32_t)(gg & 1) * P_BBUF;
            #pragma unroll
            for (int ks = 0; ks < 2; ++ks) {
                const int kA = c * 32 + ks * 16;
                uint32_t ah[2][4], al[2][4];
                #pragma unroll
                for (int mt = 0; mt < 2; ++mt) {
                    uint32_t aaddr = sb + P_AHI +
                        (uint32_t)((wr * 32 + mt * 16 + lrow) * AROW2 + (kA + lcol) * 2);
                    ldsm_x4(ah[mt][0], ah[mt][1], ah[mt][2], ah[mt][3], aaddr);
                    ldsm_x4(al[mt][0], al[mt][1], al[mt][2], al[mt][3],
                            aaddr + (P_ALO - P_AHI));
                }
                #pragma unroll
                for (int np = 0; np < 4; ++np) {
                    uint32_t baddr = bbase +
                        (uint32_t)((wc * 64 + np * 16 + lrow) * 80 + (ks * 16 + lcol) * 2);
                    uint32_t bh0, bh1, bh2, bh3;
                    ldsm_x4(bh0, bh1, bh2, bh3, baddr);
                    const int nb = np * 2;
                    #pragma unroll
                    for (int mt = 0; mt < 2; ++mt) {
                        mma_f16(acc[mt][nb],     ah[mt], bh0, bh2);
                        mma_f16(acc[mt][nb + 1], ah[mt], bh1, bh3);
                        mma_f16(acc[mt][nb],     al[mt], bh0, bh2);
                        mma_f16(acc[mt][nb + 1], al[mt], bh1, bh3);
                    }
                }
            }
            __syncthreads();
        }

        #pragma unroll
        for (int mt = 0; mt < 2; ++mt)
            #pragma unroll
            for (int nt = 0; nt < 8; ++nt) {
                int cc = wc * 64 + nt * 8 + 2 * (lane & 3);
                int r0 = wr * 32 + mt * 16 + (lane >> 2);
                int r1 = r0 + 8;
                float* d = acc[mt][nt];
                float bb0 = (h == 0) ? b0s[cc]      : (h == 2) ? ub0s[cc]     : 0.f;
                float bb1 = (h == 0) ? b0s[cc + 1]  : (h == 2) ? ub0s[cc + 1] : 0.f;
                int n0 = tile0 + r0, n1 = tile0 + r1;
                if (h < 2) {
                    int co = h * 256 + cc;
                    if (n0 < NN)
                        *reinterpret_cast<uint32_t*>(g_PQh + (size_t)n0 * 512 + co) =
                            pack_f16(d[0] + bb0, d[1] + bb1);
                    if (n1 < NN)
                        *reinterpret_cast<uint32_t*>(g_PQh + (size_t)n1 * 512 + co) =
                            pack_f16(d[2] + bb0, d[3] + bb1);
                } else {
                    if (n0 < NN)
                        *reinterpret_cast<float2*>(g_R + (size_t)n0 * HH + cc) =
                            make_float2(d[0] + bb0, d[1] + bb1);
                    if (n1 < NN)
                        *reinterpret_cast<float2*>(g_R + (size_t)n1 * HH + cc) =
                            make_float2(d[2] + bb0, d[3] + bb1);
                }
            }
    }
}

// ============== edge kernel (persistent, FOUR independent groups) ===========
// PQ fp16 gather -> hadd2/hmax2 -> A single fp16. 4-buffer A ring, 2-chunk
// barrier phases (5 barriers/tile). W1 resident fp16 (80 KB).
#define TME    32                      // edge rows per group-tile
#define E_B1   0                       // 128 floats
#define E_TO   512                     // 8 x 32 ints: [g][parity]
#define E_A    4096                    // per group: 4 bufs x 2560B (ring)
#define E_B    (4096 + 40960)          // 45056; B: 8 chunks * 10240 (fp16)
#define E_SMEM (45056 + 81920)         // 126976

#define EDGE_T32 (NE / TME)            // 18750

__global__ void __launch_bounds__(512, 1) edge_kernel(
    const int* __restrict__ from_idx, const int* __restrict__ to_idx,
    const float* __restrict__ b1)
{
    extern __shared__ char smc[];
    const uint32_t sb = smem_u32(smc);
    const int tid  = threadIdx.x;
    const int wid  = tid >> 5;
    const int lane = tid & 31;
    const int g    = wid >> 2;            // group 0..3
    const int wc   = wid & 3;             // col group 0..3 (32 cols each)
    const int lrow = ((lane >> 3) & 1) * 8 + (lane & 7);
    const int lcol = (lane >> 4) * 8;
    const int barid = 1 + g;

    float* b1s = reinterpret_cast<float*>(smc + E_B1);
    if (tid < 128) b1s[tid] = b1[tid];

    // ---- stage resident W1 (fp16) once ----
    #pragma unroll
    for (int i = 0; i < 8; ++i) {
        int idx = tid + i * 512;          // c*512 + row*4 + seg
        int c = idx >> 9, rs = idx & 511;
        int row = rs >> 2, seg = rs & 3;
        uint32_t d = sb + E_B + (uint32_t)(c * 10240 + row * 80 + seg * 16);
        cpa16(d, g_mW1f + row * HH + c * 32 + seg * 8);
    }
    CP_COMMIT();
    CP_WAIT(0);
    __syncthreads();                      // last full-CTA sync

    // hoist bias values into registers (constant across tiles)
    float bv0[4], bv1[4];
    #pragma unroll
    for (int nt = 0; nt < 4; ++nt) {
        int cc = wc * 32 + nt * 8 + 2 * (lane & 3);
        bv0[nt] = b1s[cc];
        bv1[nt] = b1s[cc + 1];
    }

    const uint4* pqh = reinterpret_cast<const uint4*>(g_PQh);
    const int ptid = tid & 127;           // group-local thread id
    const int r  = ptid >> 2;             // local row 0..31
    const int sg = ptid & 3;              // seg: 8 halves per sg per chunk
    const int ga = E_A + g * 10240;       // group A ring (4 x 2560B)
    const int off = r * 80 + sg * 16;     // byte off within A buf

    int tile = blockIdx.x * 4 + g;
    int fr = 0, to = 0;
    if (tile < EDGE_T32) {
        fr = from_idx[tile * TME + r];
        to = to_idx[tile * TME + r];
    }

    int tcnt = 0;
    for (; tile < EDGE_T32; tile += gridDim.x * 4, ++tcnt) {
        int* stob = reinterpret_cast<int*>(smc + E_TO + (g * 2 + (tcnt & 1)) * 128);
        if (sg == 0) stob[r] = to;

        // uint4 units: P row = node*64, Q row = node*64 + 32; chunk c at +c*4
        const size_t prow = (size_t)fr * 64 + sg;
        const size_t qrow = (size_t)to * 64 + 32 + sg;

        // produce chunks 0,1 into bufs 0,1
        #pragma unroll
        for (int c0 = 0; c0 < 2; ++c0) {
            uint4 P = pqh[prow + c0 * 4];
            uint4 Q = pqh[qrow + c0 * 4];
            *reinterpret_cast<uint4*>(smc + ga + c0 * 2560 + off) = relu_add_h8(P, Q);
        }
        bar_q(barid);

        // prefetch next tile's indices (latency hidden under MMA phases)
        int frN = 0, toN = 0;
        {
            int tnext = tile + gridDim.x * 4;
            if (tnext < EDGE_T32) {
                frN = from_idx[tnext * TME + r];
                toN = to_idx[tnext * TME + r];
            }
        }

        float ac2[2][4][4];
        #pragma unroll
        for (int m = 0; m < 2; ++m)
            #pragma unroll
            for (int n = 0; n < 4; ++n)
                #pragma unroll
                for (int q = 0; q < 4; ++q) ac2[m][n][q] = 0.f;

        #pragma unroll
        for (int p = 0; p < 4; ++p) {
            // issue next phase's gathers (2 chunks)
            uint4 P0, Q0, P1, Q1;
            if (p < 3) {
                P0 = pqh[prow + (2 * p + 2) * 4];
                Q0 = pqh[qrow + (2 * p + 2) * 4];
                P1 = pqh[prow + (2 * p + 3) * 4];
                Q1 = pqh[qrow + (2 * p + 3) * 4];
            }
            // MMA chunks 2p, 2p+1
            #pragma unroll
            for (int cc2 = 0; cc2 < 2; ++cc2) {
                const int c = 2 * p + cc2;
                const uint32_t abase = sb + (uint32_t)(ga + (c & 3) * 2560);
                const uint32_t bbase = sb + E_B + (uint32_t)(c * 10240);
                #pragma unroll
                for (int ks = 0; ks < 2; ++ks) {
                    uint32_t ah[2][4];
                    #pragma unroll
                    for (int mt = 0; mt < 2; ++mt) {
                        uint32_t aaddr = abase +
                            (uint32_t)((mt * 16 + lrow) * 80 + (ks * 16 + lcol) * 2);
                        ldsm_x4(ah[mt][0], ah[mt][1], ah[mt][2], ah[mt][3], aaddr);
                    }
                    #pragma unroll
                    for (int np = 0; np < 2; ++np) {
                        uint32_t baddr = bbase +
                            (uint32_t)((wc * 32 + np * 16 + lrow) * 80 +
                                       (ks * 16 + lcol) * 2);
                        uint32_t bh0, bh1, bh2, bh3;
                        ldsm_x4(bh0, bh1, bh2, bh3, baddr);
                        const int nb = np * 2;
                        #pragma unroll
                        for (int mt = 0; mt < 2; ++mt) {
                            mma_f16(ac2[mt][nb],     ah[mt], bh0, bh2);
                            mma_f16(ac2[mt][nb + 1], ah[mt], bh1, bh3);
                        }
                    }
                }
            }
            // store next phase's chunks into ring bufs
            if (p < 3) {
                const int b0i = (2 * p + 2) & 3, b1i = (2 * p + 3) & 3;
                *reinterpret_cast<uint4*>(smc + ga + b0i * 2560 + off) =
                    relu_add_h8(P0, Q0);
                *reinterpret_cast<uint4*>(smc + ga + b1i * 2560 + off) =
                    relu_add_h8(P1, Q1);
            }
            bar_q(barid);
        }

        // ---- epilogue: bias+relu, vectorized red scatter ----
        const int* stor =
            reinterpret_cast<const int*>(smc + E_TO + (g * 2 + (tcnt & 1)) * 128);
        #pragma unroll
        for (int mt = 0; mt < 2; ++mt)
            #pragma unroll
            for (int nt = 0; nt < 4; ++nt) {
                int cc = wc * 32 + nt * 8 + 2 * (lane & 3);
                int r0 = mt * 16 + (lane >> 2);
                int r1 = r0 + 8;
                float* d = ac2[mt][nt];
                float v0 = fmaxf(d[0] + bv0[nt], 0.f), v1 = fmaxf(d[1] + bv1[nt], 0.f);
                float v2 = fmaxf(d[2] + bv0[nt], 0.f), v3 = fmaxf(d[3] + bv1[nt], 0.f);
                red_add2(g_agg + (size_t)stor[r0] * DD + cc, v0, v1);
                red_add2(g_agg + (size_t)stor[r1] * DD + cc, v2, v3);
            }

        fr = frN;
        to = toN;
    }
}

// ============================ node kernel (K-folded) ========================
// S = agg@uW0a (K=128); h = relu(S + R[n]); out = feat + relu(h@uW1 + b1)
// A: fp16 hi/lo, B: single fp16 -> 2-pass mma_f16
#define SM_B1   1024
#define SM_AHI  4096
#define SM_ALO  (4096 + 67584)          // 71680
#define SM_B    (71680 + 67584)         // 139264
#define N_BBUF  20480
#define N_SMEM  (139264 + 2 * N_BBUF)   // 180224
#define AROW 528

__global__ void __launch_bounds__(512, 1) node_kernel(
    const float* __restrict__ feat,
    const float* __restrict__ b1,
    float* __restrict__ outp)
{
    extern __shared__ char smc[];
    const uint32_t sb = smem_u32(smc);
    const int tid  = threadIdx.x;
    const int wid  = tid >> 5;
    const int lane = tid & 31;
    const int wr   = wid & 3;
    const int wc   = wid >> 2;
    const int lrow = ((lane >> 3) & 1) * 8 + (lane & 7);
    const int lcol = (lane >> 4) * 8;

    float* b1s = reinterpret_cast<float*>(smc + SM_B1);

    const int tile0 = blockIdx.x * TM;

    if (tid < 128) b1s[tid] = b1[tid];

    stage_bf(sb + SM_B, tid, g_uaf, 0, 0, 256, DD);
    CP_COMMIT();
    __syncthreads();

    // gather agg tile [128 x 128]
    {
        const float4* a4 = reinterpret_cast<const float4*>(g_agg);
        #pragma unroll
        for (int it = 0; it < 8; ++it) {
            int ci = tid + it * 512;
            int r  = ci >> 5;
            int c4 = ci & 31;
            int node = tile0 + r;
            float4 v = make_float4(0.f, 0.f, 0.f, 0.f);
            if (node < NN) v = a4[(size_t)node * 32 + c4];
            split_store_h(smc, SM_AHI, SM_ALO, r * AROW + c4 * 8, v);
        }
    }
    __syncthreads();

    // GEMM1: S = agg@uW0a, K=128 -> 4 chunks
    float acc[2][8][4];
    #pragma unroll
    for (int m = 0; m < 2; ++m)
        #pragma unroll
        for (int n = 0; n < 8; ++n)
            #pragma unroll
            for (int q = 0; q < 4; ++q) acc[m][n][q] = 0.f;

    for (int c = 0; c < 4; ++c) {
        if (c < 3)
            stage_bf(sb + SM_B + (uint32_t)((c + 1) & 1) * N_BBUF, tid,
                     g_uaf, 0, c + 1, 256, DD);
        CP_COMMIT();
        CP_WAIT(1);
        __syncthreads();
        const uint32_t bbase = sb + SM_B + (uint32_t)(c & 1) * N_BBUF;
        #pragma unroll
        for (int ks = 0; ks < 2; ++ks) {
            const int kA = c * 32 + ks * 16;
            uint32_t ah[2][4], al[2][4];
            #pragma unroll
            for (int mt = 0; mt < 2; ++mt) {
                uint32_t aaddr = sb + SM_AHI +
                    (uint32_t)((wr * 32 + mt * 16 + lrow) * AROW + (kA + lcol) * 2);
                ldsm_x4(ah[mt][0], ah[mt][1], ah[mt][2], ah[mt][3], aaddr);
                ldsm_x4(al[mt][0], al[mt][1], al[mt][2], al[mt][3],
                        aaddr + (SM_ALO - SM_AHI));
            }
            #pragma unroll
            for (int np = 0; np < 4; ++np) {
                uint32_t baddr = bbase +
                    (uint32_t)((wc * 64 + np * 16 + lrow) * 80 + (ks * 16 + lcol) * 2);
                uint32_t bh0, bh1, bh2, bh3;
                ldsm_x4(bh0, bh1, bh2, bh3, baddr);
                const int nb = np * 2;
                #pragma unroll
                for (int mt = 0; mt < 2; ++mt) {
                    mma_f16(acc[mt][nb],     ah[mt], bh0, bh2);
                    mma_f16(acc[mt][nb + 1], ah[mt], bh1, bh3);
                    mma_f16(acc[mt][nb],     al[mt], bh0, bh2);
                    mma_f16(acc[mt][nb + 1], al[mt], bh1, bh3);
                }
            }
        }
        __syncthreads();
    }

    stage_bf(sb + SM_B, tid, g_uW1f, 0, 0, 128, HH);
    CP_COMMIT();

    // epilogue1: h = relu(S + R[n]) back into A tiles (fp16 hi/lo)
    #pragma unroll
    for (int mt = 0; mt < 2; ++mt)
        #pragma unroll
        for (int nt = 0; nt < 8; ++nt) {
            int cc = wc * 64 + nt * 8 + 2 * (lane & 3);
            int r0 = wr * 32 + mt * 16 + (lane >> 2);
            int n0 = tile0 + r0, n1 = n0 + 8;
            float* d = acc[mt][nt];
            float2 R0 = make_float2(0.f, 0.f), R1 = make_float2(0.f, 0.f);
            if (n0 < NN) R0 = *reinterpret_cast<const float2*>(g_R + (size_t)n0 * HH + cc);
            if (n1 < NN) R1 = *reinterpret_cast<const float2*>(g_R + (size_t)n1 * HH + cc);
            float v0 = fmaxf(d[0] + R0.x, 0.f), v1 = fmaxf(d[1] + R0.y, 0.f);
            float v2 = fmaxf(d[2] + R1.x, 0.f), v3 = fmaxf(d[3] + R1.y, 0.f);
            __half h0 = __float2half_rn(v0), h1 = __float2half_rn(v1);
            __half h2 = __float2half_rn(v2), h3 = __float2half_rn(v3);
            int o0 = r0 * AROW + cc * 2;
            int o1 = (r0 + 8) * AROW + cc * 2;
            *reinterpret_cast<uint32_t*>(smc + SM_AHI + o0) = pack_f16(v0, v1);
            *reinterpret_cast<uint32_t*>(smc + SM_AHI + o1) = pack_f16(v2, v3);
            *reinterpret_cast<uint32_t*>(smc + SM_ALO + o0) =
                pack_f16(v0 - __half2float(h0), v1 - __half2float(h1));
            *reinterpret_cast<uint32_t*>(smc + SM_ALO + o1) =
                pack_f16(v2 - __half2float(h2), v3 - __half2float(h3));
        }

    // GEMM2: M = h@uW1, K=256 -> 8 chunks
    float ac2[2][4][4];
    #pragma unroll
    for (int m = 0; m < 2; ++m)
        #pragma unroll
        for (int n = 0; n < 4; ++n)
            #pragma unroll
            for (int q = 0; q < 4; ++q) ac2[m][n][q] = 0.f;

    for (int c = 0; c < 8; ++c) {
        if (c < 7)
            stage_bf(sb + SM_B + (uint32_t)((c + 1) & 1) * N_BBUF, tid,
                     g_uW1f, 0, c + 1, 128, HH);
        CP_COMMIT();
        CP_WAIT(1);
        __syncthreads();
        const uint32_t bbase = sb + SM_B + (uint32_t)(c & 1) * N_BBUF;
        #pragma unroll
        for (int ks = 0; ks < 2; ++ks) {
            const int kA = c * 32 + ks * 16;
            uint32_t ah[2][4], al[2][4];
            #pragma unroll
            for (int mt = 0; mt < 2; ++mt) {
                uint32_t aaddr = sb + SM_AHI +
                    (uint32_t)((wr * 32 + mt * 16 + lrow) * AROW + (kA + lcol) * 2);
                ldsm_x4(ah[mt][0], ah[mt][1], ah[mt][2], ah[mt][3], aaddr);
                ldsm_x4(al[mt][0], al[mt][1], al[mt][2], al[mt][3],
                        aaddr + (SM_ALO - SM_AHI));
            }
            #pragma unroll
            for (int np = 0; np < 2; ++np) {
                uint32_t baddr = bbase +
                    (uint32_t)((wc * 32 + np * 16 + lrow) * 80 + (ks * 16 + lcol) * 2);
                uint32_t bh0, bh1, bh2, bh3;
                ldsm_x4(bh0, bh1, bh2, bh3, baddr);
                const int nb = np * 2;
                #pragma unroll
                for (int mt = 0; mt < 2; ++mt) {
                    mma_f16(ac2[mt][nb],     ah[mt], bh0, bh2);
                    mma_f16(ac2[mt][nb + 1], ah[mt], bh1, bh3);
                    mma_f16(ac2[mt][nb],     al[mt], bh0, bh2);
                    mma_f16(ac2[mt][nb + 1], al[mt], bh1, bh3);
                }
            }
        }
        __syncthreads();
    }

    // epilogue2: residual store
    #pragma unroll
    for (int mt = 0; mt < 2; ++mt)
        #pragma unroll
        for (int nt = 0; nt < 4; ++nt) {
            int cc = wc * 32 + nt * 8 + 2 * (lane & 3);
            int r0 = wr * 32 + mt * 16 + (lane >> 2);
            int r1 = r0 + 8;
            float* d = ac2[mt][nt];
            float v0 = fmaxf(d[0] + b1s[cc], 0.f), v1 = fmaxf(d[1] + b1s[cc + 1], 0.f);
            float v2 = fmaxf(d[2] + b1s[cc], 0.f), v3 = fmaxf(d[3] + b1s[cc + 1], 0.f);
            int n0 = tile0 + r0, n1 = tile0 + r1;
            if (n0 < NN) {
                float2 f = *reinterpret_cast<const float2*>(feat + (size_t)n0 * DD + cc);
                *reinterpret_cast<float2*>(outp + (size_t)n0 * DD + cc) =
                    make_float2(f.x + v0, f.y + v1);
            }
            if (n1 < NN) {
                float2 f = *reinterpret_cast<const float2*>(feat + (size_t)n1 * DD + cc);
                *reinterpret_cast<float2*>(outp + (size_t)n1 * DD + cc) =
                    make_float2(f.x + v2, f.y + v3);
            }
        }
}

// ============================== host launch =================================
extern "C" void kernel_launch(void* const* d_in, const int* in_sizes, int n_in,
                              void* d_out, int out_size)
{
    const float* feat  = (const float*)d_in[0];
    const int*   f_idx = (const int*)  d_in[1];
    const int*   t_idx = (const int*)  d_in[2];
    const float* msgW0 = (const float*)d_in[3];
    const float* msgb0 = (const float*)d_in[4];
    const float* msgW1 = (const float*)d_in[5];
    const float* msgb1 = (const float*)d_in[6];
    const float* updW0 = (const float*)d_in[7];
    const float* updb0 = (const float*)d_in[8];
    const float* updW1 = (const float*)d_in[9];
    const float* updb1 = (const float*)d_in[10];
    float* out = (float*)d_out;

    cudaFuncSetAttribute(pq_kernel,   cudaFuncAttributeMaxDynamicSharedMemorySize, P_SMEM);
    cudaFuncSetAttribute(edge_kernel, cudaFuncAttributeMaxDynamicSharedMemorySize, E_SMEM);
    cudaFuncSetAttribute(node_kernel, cudaFuncAttributeMaxDynamicSharedMemorySize, N_SMEM);

    conv_w_kernel<<<768, 256>>>(msgW0, updW0, msgW1, updW1);
    zero_agg_kernel<<<1024, 256>>>();

    const int pq_tiles   = (NN + TM - 1) / TM;  // 391
    const int node_tiles = (NN + TM - 1) / TM;  // 391

    pq_kernel<<<pq_tiles, 512, P_SMEM>>>(feat, msgb0, updb0);
    edge_kernel<<<152, 512, E_SMEM>>>(f_idx, t_idx, msgb1);
    node_kernel<<<node_tiles, 512, N_SMEM>>>(feat, updb1, out);
}